// round 3
// baseline (speedup 1.0000x reference)
#include <cuda_runtime.h>
#include <math.h>

// Problem constants
#define B_   4
#define LV   2048
#define LE   64
#define LT   2112      // LV + LE
#define D_   960
#define H_   15
#define KVH_ 5
#define HD_  64
#define NKV  320       // KVH_*HD_

// Scratch (device globals: allocation-free per harness rules)
__device__ float g_xn[B_*LT*D_];     // rmsnormed hidden
__device__ float g_q [B_*LT*D_];     // H*HD, head-major
__device__ float g_k [B_*LT*NKV];
__device__ float g_v [B_*LT*NKV];
__device__ float g_at[B_*LT*D_];     // attention output (head-major)

// ---------------------------------------------------------------------------
// RMSNorm: one block per row -> g_xn
// ---------------------------------------------------------------------------
__global__ void __launch_bounds__(256) rmsnorm_kernel(
    const float* __restrict__ hv, const float* __restrict__ he,
    const float* __restrict__ lnv, const float* __restrict__ lne)
{
    int r = blockIdx.x;
    int b = r / LT, l = r % LT;
    const float* src; const float* w;
    if (l < LV) { src = hv + ((size_t)b*LV + l)*D_; w = lnv; }
    else        { src = he + ((size_t)b*LE + (l-LV))*D_; w = lne; }
    int tid = threadIdx.x;
    float ss = 0.f;
    for (int i = tid; i < D_; i += 256) { float x = src[i]; ss += x*x; }
    #pragma unroll
    for (int o = 16; o > 0; o >>= 1) ss += __shfl_xor_sync(0xffffffffu, ss, o);
    __shared__ float red[8];
    if ((tid & 31) == 0) red[tid >> 5] = ss;
    __syncthreads();
    float tot = 0.f;
    #pragma unroll
    for (int i = 0; i < 8; i++) tot += red[i];
    float inv = rsqrtf(tot * (1.0f/D_) + 1e-6f);
    float* dst = g_xn + (size_t)r * D_;
    for (int i = tid; i < D_; i += 256) dst[i] = src[i] * inv * w[i];
}

// ---------------------------------------------------------------------------
// GEMM (templated src/dst so no symbol addresses are needed on host):
//   SRC: 0 = g_xn, 1 = g_at
//   DST: 0 = g_q, 1 = g_k, 2 = g_v, 3 = Out param
// C[b*LT+row0+m, :N] = A[...] @ W[960, N] (+ residual R)
// Tile 64x64, K-tile 32, 256 threads, 4x4 per thread.
// ---------------------------------------------------------------------------
template<int SRC, int DST>
__global__ void __launch_bounds__(256) gemm_kernel(
    const float* __restrict__ W, float* __restrict__ Out,
    const float* __restrict__ R, int N, int row0, int Rrows)
{
    const int K = D_;
    const float* A = (SRC == 0) ? g_xn : g_at;
    float* C;
    if      (DST == 0) C = g_q;
    else if (DST == 1) C = g_k;
    else if (DST == 2) C = g_v;
    else               C = Out;

    int b  = blockIdx.z;
    int m0 = blockIdx.y * 64;
    int n0 = blockIdx.x * 64;
    const float* Ab = A + ((size_t)b*LT + row0 + m0) * K;
    __shared__ float As[32][64];   // [k][m] (transposed)
    __shared__ float Ws[32][64];   // [k][n]
    int tid = threadIdx.x;
    int tx = tid & 15, ty = tid >> 4;
    int a_r0 = tid >> 3,        a_c0 = (tid & 7) << 2;
    int a_r1 = (tid+256) >> 3,  a_c1 = ((tid+256) & 7) << 2;
    int w_r0 = tid >> 4,        w_c0 = (tid & 15) << 2;
    int w_r1 = (tid+256) >> 4,  w_c1 = ((tid+256) & 15) << 2;
    float acc[4][4] = {};
    for (int k0 = 0; k0 < K; k0 += 32) {
        {
            float4 v0 = *(const float4*)(Ab + (size_t)a_r0*K + k0 + a_c0);
            float4 v1 = *(const float4*)(Ab + (size_t)a_r1*K + k0 + a_c1);
            As[a_c0+0][a_r0] = v0.x; As[a_c0+1][a_r0] = v0.y;
            As[a_c0+2][a_r0] = v0.z; As[a_c0+3][a_r0] = v0.w;
            As[a_c1+0][a_r1] = v1.x; As[a_c1+1][a_r1] = v1.y;
            As[a_c1+2][a_r1] = v1.z; As[a_c1+3][a_r1] = v1.w;
            *(float4*)&Ws[w_r0][w_c0] = *(const float4*)(W + (size_t)(k0+w_r0)*N + n0 + w_c0);
            *(float4*)&Ws[w_r1][w_c1] = *(const float4*)(W + (size_t)(k0+w_r1)*N + n0 + w_c1);
        }
        __syncthreads();
        #pragma unroll
        for (int kk = 0; kk < 32; kk++) {
            float4 a4 = *(const float4*)&As[kk][ty<<2];
            float4 w4 = *(const float4*)&Ws[kk][tx<<2];
            float av[4] = {a4.x,a4.y,a4.z,a4.w};
            float wv[4] = {w4.x,w4.y,w4.z,w4.w};
            #pragma unroll
            for (int i2 = 0; i2 < 4; i2++)
                #pragma unroll
                for (int j2 = 0; j2 < 4; j2++)
                    acc[i2][j2] += av[i2]*wv[j2];
        }
        __syncthreads();
    }
    #pragma unroll
    for (int i2 = 0; i2 < 4; i2++) {
        int m = m0 + (ty<<2) + i2;
        float4 o;
        o.x = acc[i2][0]; o.y = acc[i2][1]; o.z = acc[i2][2]; o.w = acc[i2][3];
        if (R) {
            float4 rv = *(const float4*)(R + ((size_t)b*Rrows + m)*D_ + n0 + (tx<<2));
            o.x += rv.x; o.y += rv.y; o.z += rv.z; o.w += rv.w;
        }
        *(float4*)(C + ((size_t)b*LT + row0 + m)*N + n0 + (tx<<2)) = o;
    }
}

// ---------------------------------------------------------------------------
// RoPE in-place on g_q (15 heads) and g_k (5 heads). One warp per (row, head).
// ---------------------------------------------------------------------------
__global__ void __launch_bounds__(256) rope_kernel(
    const int* __restrict__ pos_v, const int* __restrict__ pos_e)
{
    int w    = blockIdx.x * 8 + (threadIdx.x >> 5);
    int lane = threadIdx.x & 31;
    int row = w / 20;
    int hh  = w % 20;
    int b = row / LT, l = row % LT;
    int p = (l < LV) ? pos_v[b*LV + l] : pos_e[b*LE + (l - LV)];
    float ts  = powf(10000.0f, (float)lane * (1.0f/32.0f));
    float rad = (float)p / ts;
    float sn, cs;
    sincosf(rad, &sn, &cs);
    float* base = (hh < H_) ? (g_q + (size_t)row*D_  + hh*HD_)
                            : (g_k + (size_t)row*NKV + (hh - H_)*HD_);
    float x1 = base[lane], x2 = base[lane + 32];
    base[lane]      = x1*cs - x2*sn;
    base[lane + 32] = x2*cs + x1*sn;
}

// ---------------------------------------------------------------------------
// Flash attention, 64q x 32k tiles, fp32, STATIC smem (~40.3KB, no attribute).
// Grid (33 q-tiles, 15 heads, 4 batches).
// q-tiles 0..31 = VLM rows: keys 0..2047 (64 k-tiles).
// q-tile 32     = expert rows: keys 0..2047 full + causal expert keys (66 k-tiles).
// ---------------------------------------------------------------------------
__global__ void __launch_bounds__(256) attn_kernel()
{
    __shared__ float Qst[64*64];   // [d][qr]
    __shared__ float Kst[64*32];   // [d][kc]
    __shared__ float Vs [32*64];   // [kc][d]
    __shared__ float Ps [32*65];   // [kc][qr] (pad 1)

    int qt = blockIdx.x, h = blockIdx.y, b = blockIdx.z;
    int kvh = h / 3;
    int tid = threadIdx.x;
    int tx = tid & 15, ty = tid >> 4;
    int q0 = qt * 64;

    // load + scale + transpose Q tile (64x64)
    #pragma unroll
    for (int i = 0; i < 4; i++) {
        int j  = tid + i*256;
        int rr = j >> 4;
        int c4 = (j & 15) << 2;
        float4 v = *(const float4*)(g_q + ((size_t)(b*LT + q0 + rr))*D_ + h*HD_ + c4);
        Qst[(c4+0)*64+rr] = v.x*0.125f;
        Qst[(c4+1)*64+rr] = v.y*0.125f;
        Qst[(c4+2)*64+rr] = v.z*0.125f;
        Qst[(c4+3)*64+rr] = v.w*0.125f;
    }
    float m_i[4], l_i[4], acc[4][4];
    #pragma unroll
    for (int i = 0; i < 4; i++) {
        m_i[i] = -1e30f; l_i[i] = 0.f;
        #pragma unroll
        for (int j = 0; j < 4; j++) acc[i][j] = 0.f;
    }
    int nkt = (qt == 32) ? 66 : 64;
    __syncthreads();

    for (int kt = 0; kt < nkt; kt++) {
        // load K (transposed) and V tiles (32 rows x 64 cols)
        #pragma unroll
        for (int i = 0; i < 2; i++) {
            int j  = tid + i*256;
            int rr = j >> 4;             // 0..31
            int c4 = (j & 15) << 2;
            size_t off = ((size_t)(b*LT + kt*32 + rr))*NKV + kvh*HD_ + c4;
            float4 kk = *(const float4*)(g_k + off);
            Kst[(c4+0)*32+rr] = kk.x;
            Kst[(c4+1)*32+rr] = kk.y;
            Kst[(c4+2)*32+rr] = kk.z;
            Kst[(c4+3)*32+rr] = kk.w;
            *(float4*)&Vs[rr*64 + c4] = *(const float4*)(g_v + off);
        }
        __syncthreads();

        // S = (Q*scale) K^T : each thread 4 q-rows x 2 k-cols
        float s[4][2] = {};
        #pragma unroll 8
        for (int d = 0; d < 64; d++) {
            float4 q4 = *(const float4*)&Qst[d*64 + (ty<<2)];
            float2 k2 = *(const float2*)&Kst[d*32 + (tx<<1)];
            float qa[4] = {q4.x,q4.y,q4.z,q4.w};
            #pragma unroll
            for (int i = 0; i < 4; i++) {
                s[i][0] += qa[i]*k2.x;
                s[i][1] += qa[i]*k2.y;
            }
        }
        // causal mask inside expert/expert sub-blocks
        if (qt == 32 && kt >= 64) {
            int kbase = (kt - 64) * 32;
            #pragma unroll
            for (int i = 0; i < 4; i++) {
                int qe = (ty<<2) + i;
                #pragma unroll
                for (int j = 0; j < 2; j++)
                    if (kbase + (tx<<1) + j > qe) s[i][j] = -1e30f;
            }
        }
        // online softmax: rows owned by 16 tx-lanes (2 cols each)
        #pragma unroll
        for (int i = 0; i < 4; i++) {
            float rm = fmaxf(s[i][0], s[i][1]);
            #pragma unroll
            for (int o = 1; o < 16; o <<= 1) rm = fmaxf(rm, __shfl_xor_sync(0xffffffffu, rm, o));
            float mn = fmaxf(m_i[i], rm);
            float alpha = __expf(m_i[i] - mn);
            float p0 = __expf(s[i][0] - mn);
            float p1 = __expf(s[i][1] - mn);
            s[i][0] = p0; s[i][1] = p1;
            float sum = p0 + p1;
            #pragma unroll
            for (int o = 1; o < 16; o <<= 1) sum += __shfl_xor_sync(0xffffffffu, sum, o);
            l_i[i] = l_i[i]*alpha + sum;
            m_i[i] = mn;
            #pragma unroll
            for (int j = 0; j < 4; j++) acc[i][j] *= alpha;
        }
        // P transposed to smem: Ps[kc][qr]
        #pragma unroll
        for (int i = 0; i < 4; i++) {
            Ps[((tx<<1)+0)*65 + (ty<<2)+i] = s[i][0];
            Ps[((tx<<1)+1)*65 + (ty<<2)+i] = s[i][1];
        }
        __syncthreads();
        // O += P V
        #pragma unroll 4
        for (int kc = 0; kc < 32; kc++) {
            float4 v4 = *(const float4*)&Vs[kc*64 + (tx<<2)];
            float va[4] = {v4.x,v4.y,v4.z,v4.w};
            float pv[4];
            #pragma unroll
            for (int i = 0; i < 4; i++) pv[i] = Ps[kc*65 + (ty<<2)+i];
            #pragma unroll
            for (int i = 0; i < 4; i++)
                #pragma unroll
                for (int j = 0; j < 4; j++)
                    acc[i][j] += pv[i]*va[j];
        }
        __syncthreads();
    }
    #pragma unroll
    for (int i = 0; i < 4; i++) {
        float inv = 1.0f / l_i[i];
        float4 o;
        o.x = acc[i][0]*inv; o.y = acc[i][1]*inv;
        o.z = acc[i][2]*inv; o.w = acc[i][3]*inv;
        *(float4*)(g_at + ((size_t)(b*LT + q0 + (ty<<2)+i))*D_ + h*HD_ + (tx<<2)) = o;
    }
}

// ---------------------------------------------------------------------------
// kernel_launch: ONLY kernel launches (graph-capture friendly).
// ---------------------------------------------------------------------------
extern "C" void kernel_launch(void* const* d_in, const int* in_sizes, int n_in,
                              void* d_out, int out_size)
{
    const float* hv   = (const float*)d_in[0];
    const float* he   = (const float*)d_in[1];
    const float* lnv  = (const float*)d_in[2];
    const float* wq_v = (const float*)d_in[3];
    const float* wk_v = (const float*)d_in[4];
    const float* wv_v = (const float*)d_in[5];
    const float* wo_v = (const float*)d_in[6];
    const float* lne  = (const float*)d_in[7];
    const float* wq_e = (const float*)d_in[8];
    const float* wk_e = (const float*)d_in[9];
    const float* wv_e = (const float*)d_in[10];
    const float* wo_e = (const float*)d_in[11];
    const int*   posv = (const int*)d_in[12];
    const int*   pose = (const int*)d_in[13];
    float* out = (float*)d_out;

    rmsnorm_kernel<<<B_*LT, 256>>>(hv, he, lnv, lne);

    // QKV projections (VLM rows 0..2047, expert rows 2048..2111)
    gemm_kernel<0,0><<<dim3(15,32,4),256>>>(wq_v, nullptr, nullptr, 960, 0,    0);
    gemm_kernel<0,1><<<dim3( 5,32,4),256>>>(wk_v, nullptr, nullptr, 320, 0,    0);
    gemm_kernel<0,2><<<dim3( 5,32,4),256>>>(wv_v, nullptr, nullptr, 320, 0,    0);
    gemm_kernel<0,0><<<dim3(15, 1,4),256>>>(wq_e, nullptr, nullptr, 960, 2048, 0);
    gemm_kernel<0,1><<<dim3( 5, 1,4),256>>>(wk_e, nullptr, nullptr, 320, 2048, 0);
    gemm_kernel<0,2><<<dim3( 5, 1,4),256>>>(wv_e, nullptr, nullptr, 320, 2048, 0);

    rope_kernel<<<(B_*LT*20)/8, 256>>>(posv, pose);

    attn_kernel<<<dim3(33,15,4),256>>>();

    // Output projection + residual, straight into d_out
    gemm_kernel<1,3><<<dim3(15,32,4),256>>>(wo_v, out, hv, 960, 0,    2048);
    gemm_kernel<1,3><<<dim3(15, 1,4),256>>>(wo_e, out, he, 960, 2048, 64);
}

// round 5
// speedup vs baseline: 2.6098x; 2.6098x over previous
#include <cuda_runtime.h>
#include <math.h>
#include <stdint.h>

// Problem constants
#define B_   4
#define LV   2048
#define LE   64
#define LT   2112      // LV + LE
#define D_   960
#define H_   15
#define KVH_ 5
#define HD_  64
#define NKV  320       // KVH_*HD_

// Scratch (device globals: allocation-free per harness rules)
__device__ float g_xn[B_*LT*D_];     // rmsnormed hidden
__device__ float g_q [B_*LT*D_];     // H*HD, head-major
__device__ float g_k [B_*LT*NKV];
__device__ float g_v [B_*LT*NKV];
__device__ float g_at[B_*LT*D_];     // attention output (head-major)

// ---------------------------------------------------------------------------
// tf32 helpers
// ---------------------------------------------------------------------------
__device__ __forceinline__ float f2tf(float f) {
    uint32_t u;
    asm("cvt.rna.tf32.f32 %0, %1;" : "=r"(u) : "f"(f));
    return __uint_as_float(u);
}
__device__ __forceinline__ void mma8(float* c, const uint32_t* a, uint32_t b0, uint32_t b1) {
    asm("mma.sync.aligned.m16n8k8.row.col.f32.tf32.tf32.f32 "
        "{%0,%1,%2,%3}, {%4,%5,%6,%7}, {%8,%9}, {%0,%1,%2,%3};"
        : "+f"(c[0]), "+f"(c[1]), "+f"(c[2]), "+f"(c[3])
        : "r"(a[0]), "r"(a[1]), "r"(a[2]), "r"(a[3]), "r"(b0), "r"(b1));
}
// pick slot (sel) of a 2-value pair fetched from lane src
__device__ __forceinline__ float pshfl(float v0, float v1, int src, int sel) {
    float a = __shfl_sync(0xffffffffu, v0, src);
    float b = __shfl_sync(0xffffffffu, v1, src);
    return sel ? b : a;
}

// ---------------------------------------------------------------------------
// RMSNorm: one block per row -> g_xn
// ---------------------------------------------------------------------------
__global__ void __launch_bounds__(256) rmsnorm_kernel(
    const float* __restrict__ hv, const float* __restrict__ he,
    const float* __restrict__ lnv, const float* __restrict__ lne)
{
    int r = blockIdx.x;
    int b = r / LT, l = r % LT;
    const float* src; const float* w;
    if (l < LV) { src = hv + ((size_t)b*LV + l)*D_; w = lnv; }
    else        { src = he + ((size_t)b*LE + (l-LV))*D_; w = lne; }
    int tid = threadIdx.x;
    float ss = 0.f;
    for (int i = tid; i < D_; i += 256) { float x = src[i]; ss += x*x; }
    #pragma unroll
    for (int o = 16; o > 0; o >>= 1) ss += __shfl_xor_sync(0xffffffffu, ss, o);
    __shared__ float red[8];
    if ((tid & 31) == 0) red[tid >> 5] = ss;
    __syncthreads();
    float tot = 0.f;
    #pragma unroll
    for (int i = 0; i < 8; i++) tot += red[i];
    float inv = rsqrtf(tot * (1.0f/D_) + 1e-6f);
    float* dst = g_xn + (size_t)r * D_;
    for (int i = tid; i < D_; i += 256) dst[i] = src[i] * inv * w[i];
}

// ---------------------------------------------------------------------------
// tf32 tensor-core GEMM.
//   SRC: 0 = g_xn, 1 = g_at     DST: 0 = g_q, 1 = g_k, 2 = g_v, 3 = Out
// Tile M=128, N=64, Ktile=32. 256 threads = 8 warps (4m x 2n), each warp 32x32.
// ---------------------------------------------------------------------------
template<int SRC, int DST>
__global__ void __launch_bounds__(256) gemm_tc(
    const float* __restrict__ W, float* __restrict__ Out,
    const float* __restrict__ R, int N, int row0, int mvalid, int Rrows)
{
    const float* A = (SRC == 0) ? g_xn : g_at;
    float* C;
    if      (DST == 0) C = g_q;
    else if (DST == 1) C = g_k;
    else if (DST == 2) C = g_v;
    else               C = Out;

    __shared__ float As[128*36];   // A[m][k], stride 36
    __shared__ float Ws[32*72];    // W[k][n], stride 72

    int b  = blockIdx.z;
    int mb = blockIdx.y * 128;
    int n0 = blockIdx.x * 64;
    int tid  = threadIdx.x;
    int wid  = tid >> 5, lane = tid & 31;
    int g = lane >> 2, t = lane & 3;
    int wm = wid >> 1, wn = wid & 1;

    float acc[2][4][4] = {};

    for (int k0 = 0; k0 < D_; k0 += 32) {
        #pragma unroll
        for (int i = 0; i < 4; i++) {
            int j   = tid + i*256;
            int row = j >> 3;
            int kq  = (j & 7) << 2;
            int rl  = mb + row; if (rl >= mvalid) rl = mvalid - 1;
            float4 v = *(const float4*)(A + ((size_t)(b*LT + row0 + rl))*D_ + k0 + kq);
            *(float4*)&As[row*36 + kq] = make_float4(f2tf(v.x), f2tf(v.y), f2tf(v.z), f2tf(v.w));
        }
        #pragma unroll
        for (int i = 0; i < 2; i++) {
            int j   = tid + i*256;
            int row = j >> 4;
            int c   = (j & 15) << 2;
            float4 v = *(const float4*)(W + (size_t)(k0 + row)*N + n0 + c);
            *(float4*)&Ws[row*72 + c] = make_float4(f2tf(v.x), f2tf(v.y), f2tf(v.z), f2tf(v.w));
        }
        __syncthreads();
        #pragma unroll
        for (int ks = 0; ks < 4; ks++) {
            int kb = ks*8;
            uint32_t a[2][4];
            #pragma unroll
            for (int mt = 0; mt < 2; mt++) {
                int rb = wm*32 + mt*16;
                a[mt][0] = __float_as_uint(As[(rb+g  )*36 + kb + t]);
                a[mt][1] = __float_as_uint(As[(rb+g+8)*36 + kb + t]);
                a[mt][2] = __float_as_uint(As[(rb+g  )*36 + kb + t + 4]);
                a[mt][3] = __float_as_uint(As[(rb+g+8)*36 + kb + t + 4]);
            }
            uint32_t bb[4][2];
            #pragma unroll
            for (int nt = 0; nt < 4; nt++) {
                int col = wn*32 + nt*8 + g;
                bb[nt][0] = __float_as_uint(Ws[(kb+t  )*72 + col]);
                bb[nt][1] = __float_as_uint(Ws[(kb+t+4)*72 + col]);
            }
            #pragma unroll
            for (int mt = 0; mt < 2; mt++)
                #pragma unroll
                for (int nt = 0; nt < 4; nt++)
                    mma8(acc[mt][nt], a[mt], bb[nt][0], bb[nt][1]);
        }
        __syncthreads();
    }

    #pragma unroll
    for (int mt = 0; mt < 2; mt++) {
        #pragma unroll
        for (int nt = 0; nt < 4; nt++) {
            int col = n0 + wn*32 + nt*8 + 2*t;
            int m0r = mb + wm*32 + mt*16 + g;
            if (m0r < mvalid) {
                float2 o = make_float2(acc[mt][nt][0], acc[mt][nt][1]);
                if (R) {
                    float2 rv = *(const float2*)(R + ((size_t)b*Rrows + m0r)*D_ + col);
                    o.x += rv.x; o.y += rv.y;
                }
                *(float2*)(C + ((size_t)(b*LT + row0 + m0r))*N + col) = o;
            }
            int m1r = m0r + 8;
            if (m1r < mvalid) {
                float2 o = make_float2(acc[mt][nt][2], acc[mt][nt][3]);
                if (R) {
                    float2 rv = *(const float2*)(R + ((size_t)b*Rrows + m1r)*D_ + col);
                    o.x += rv.x; o.y += rv.y;
                }
                *(float2*)(C + ((size_t)(b*LT + row0 + m1r))*N + col) = o;
            }
        }
    }
}

// ---------------------------------------------------------------------------
// RoPE in-place on g_q (15 heads) and g_k (5 heads). One warp per (row, head).
// ---------------------------------------------------------------------------
__global__ void __launch_bounds__(256) rope_kernel(
    const int* __restrict__ pos_v, const int* __restrict__ pos_e)
{
    int w    = blockIdx.x * 8 + (threadIdx.x >> 5);
    int lane = threadIdx.x & 31;
    int row = w / 20;
    int hh  = w % 20;
    int b = row / LT, l = row % LT;
    int p = (l < LV) ? pos_v[b*LV + l] : pos_e[b*LE + (l - LV)];
    float ts  = powf(10000.0f, (float)lane * (1.0f/32.0f));
    float rad = (float)p / ts;
    float sn, cs;
    sincosf(rad, &sn, &cs);
    float* base = (hh < H_) ? (g_q + (size_t)row*D_  + hh*HD_)
                            : (g_k + (size_t)row*NKV + (hh - H_)*HD_);
    float x1 = base[lane], x2 = base[lane + 32];
    base[lane]      = x1*cs - x2*sn;
    base[lane + 32] = x2*cs + x1*sn;
}

// ---------------------------------------------------------------------------
// tf32 tensor-core flash attention.
// Tile 128q x 64k, 8 warps x 16 q rows (warp-local softmax).
// K,V stored NATURAL [key][d] stride 76 (coalesced writes, conflict-free/mild
// B-frag reads). P relayout C-frag -> A-frag via quad shuffles (no smem).
// Grid (17 q-tiles, 15 heads, 4 batches); qt 16 = expert rows.
// ---------------------------------------------------------------------------
__global__ void __launch_bounds__(256) attn_tc()
{
    __shared__ float Ks[64*76];    // [key][d]
    __shared__ float Vs[64*76];    // [key][d]

    int qt = blockIdx.x, h = blockIdx.y, b = blockIdx.z;
    int kvh = h / 3;
    int tid = threadIdx.x;
    int w = tid >> 5, lane = tid & 31;
    int g = lane >> 2, t = lane & 3;
    int q0  = qt * 128;
    int qr0 = w * 16;
    bool is_exp = (qt == 16);
    int nkt = is_exp ? 33 : 32;

    // Q fragments, register resident: 8 d-ktiles x 4 regs
    uint32_t qa[8][4];
    {
        int r0 = q0 + qr0 + g;     if (r0 > LT-1) r0 = LT-1;
        int r1 = q0 + qr0 + g + 8; if (r1 > LT-1) r1 = LT-1;
        const float* p0 = g_q + ((size_t)(b*LT + r0))*D_ + h*HD_;
        const float* p1 = g_q + ((size_t)(b*LT + r1))*D_ + h*HD_;
        #pragma unroll
        for (int kt8 = 0; kt8 < 8; kt8++) {
            qa[kt8][0] = __float_as_uint(f2tf(p0[kt8*8 + t    ] * 0.125f));
            qa[kt8][1] = __float_as_uint(f2tf(p1[kt8*8 + t    ] * 0.125f));
            qa[kt8][2] = __float_as_uint(f2tf(p0[kt8*8 + t + 4] * 0.125f));
            qa[kt8][3] = __float_as_uint(f2tf(p1[kt8*8 + t + 4] * 0.125f));
        }
    }

    float o[8][4] = {};
    float m2[2] = {-1e30f, -1e30f};
    float l2[2] = {0.f, 0.f};

    int qbase = lane & ~3;          // quad base lane
    int s0 = qbase | (t >> 1);      // src lane for col t
    int s1 = qbase | ((t >> 1) + 2);// src lane for col t+4
    int sel = t & 1;

    for (int kt = 0; kt < nkt; kt++) {
        // cooperative, coalesced load of K,V tiles (natural layout)
        #pragma unroll
        for (int i = 0; i < 4; i++) {
            int j   = tid + i*256;
            int key = j >> 4;
            int dq  = (j & 15) << 2;
            size_t off = ((size_t)(b*LT + kt*64 + key))*NKV + kvh*HD_ + dq;
            float4 kk = *(const float4*)(g_k + off);
            *(float4*)&Ks[key*76 + dq] = make_float4(f2tf(kk.x), f2tf(kk.y), f2tf(kk.z), f2tf(kk.w));
            float4 vv = *(const float4*)(g_v + off);
            *(float4*)&Vs[key*76 + dq] = make_float4(f2tf(vv.x), f2tf(vv.y), f2tf(vv.z), f2tf(vv.w));
        }
        __syncthreads();

        // S = Q K^T  (16q x 64k per warp). B[k=d][n=key] = Ks[key][d].
        float sacc[8][4] = {};
        #pragma unroll
        for (int ks = 0; ks < 8; ks++) {
            int kb = ks*8;
            #pragma unroll
            for (int nt = 0; nt < 8; nt++) {
                int col = nt*8 + g;
                uint32_t b0 = __float_as_uint(Ks[col*76 + kb + t    ]);
                uint32_t b1 = __float_as_uint(Ks[col*76 + kb + t + 4]);
                mma8(sacc[nt], qa[ks], b0, b1);
            }
        }
        // causal mask in expert/expert block
        if (is_exp && kt == 32) {
            int qe0 = qr0 + g, qe1 = qe0 + 8;
            #pragma unroll
            for (int nt = 0; nt < 8; nt++) {
                int c0 = nt*8 + 2*t, c1 = c0 + 1;
                if (c0 > qe0) sacc[nt][0] = -1e30f;
                if (c1 > qe0) sacc[nt][1] = -1e30f;
                if (c0 > qe1) sacc[nt][2] = -1e30f;
                if (c1 > qe1) sacc[nt][3] = -1e30f;
            }
        }
        // online softmax per row-half (rows g and g+8)
        #pragma unroll
        for (int hh = 0; hh < 2; hh++) {
            float rm = -1e30f;
            #pragma unroll
            for (int nt = 0; nt < 8; nt++)
                rm = fmaxf(rm, fmaxf(sacc[nt][hh*2], sacc[nt][hh*2+1]));
            rm = fmaxf(rm, __shfl_xor_sync(0xffffffffu, rm, 1));
            rm = fmaxf(rm, __shfl_xor_sync(0xffffffffu, rm, 2));
            float mn = fmaxf(m2[hh], rm);
            float alpha = __expf(m2[hh] - mn);
            float sum = 0.f;
            #pragma unroll
            for (int nt = 0; nt < 8; nt++) {
                float p0 = __expf(sacc[nt][hh*2  ] - mn);
                float p1 = __expf(sacc[nt][hh*2+1] - mn);
                sacc[nt][hh*2] = p0; sacc[nt][hh*2+1] = p1;
                sum += p0 + p1;
            }
            sum += __shfl_xor_sync(0xffffffffu, sum, 1);
            sum += __shfl_xor_sync(0xffffffffu, sum, 2);
            l2[hh] = l2[hh]*alpha + sum;
            m2[hh] = mn;
            #pragma unroll
            for (int nt = 0; nt < 8; nt++) {
                o[nt][hh*2]   *= alpha;
                o[nt][hh*2+1] *= alpha;
            }
        }
        // O += P V.  P A-frag built from S C-frag via quad shuffles.
        #pragma unroll
        for (int ks = 0; ks < 8; ks++) {
            int kb = ks*8;
            uint32_t pa[4];
            pa[0] = __float_as_uint(f2tf(pshfl(sacc[ks][0], sacc[ks][1], s0, sel)));
            pa[1] = __float_as_uint(f2tf(pshfl(sacc[ks][2], sacc[ks][3], s0, sel)));
            pa[2] = __float_as_uint(f2tf(pshfl(sacc[ks][0], sacc[ks][1], s1, sel)));
            pa[3] = __float_as_uint(f2tf(pshfl(sacc[ks][2], sacc[ks][3], s1, sel)));
            #pragma unroll
            for (int nt = 0; nt < 8; nt++) {
                int col = nt*8 + g;
                uint32_t b0 = __float_as_uint(Vs[(kb+t  )*76 + col]);
                uint32_t b1 = __float_as_uint(Vs[(kb+t+4)*76 + col]);
                mma8(o[nt], pa, b0, b1);
            }
        }
        __syncthreads();
    }

    // normalize + store
    float inv0 = 1.0f / l2[0];
    float inv1 = 1.0f / l2[1];
    int r0 = q0 + qr0 + g;
    int r1 = r0 + 8;
    #pragma unroll
    for (int nt = 0; nt < 8; nt++) {
        int col = h*HD_ + nt*8 + 2*t;
        if (r0 < LT) {
            float2 ov = make_float2(o[nt][0]*inv0, o[nt][1]*inv0);
            *(float2*)(g_at + ((size_t)(b*LT + r0))*D_ + col) = ov;
        }
        if (r1 < LT) {
            float2 ov = make_float2(o[nt][2]*inv1, o[nt][3]*inv1);
            *(float2*)(g_at + ((size_t)(b*LT + r1))*D_ + col) = ov;
        }
    }
}

// ---------------------------------------------------------------------------
// kernel_launch: ONLY kernel launches (graph-capture friendly).
// ---------------------------------------------------------------------------
extern "C" void kernel_launch(void* const* d_in, const int* in_sizes, int n_in,
                              void* d_out, int out_size)
{
    const float* hv   = (const float*)d_in[0];
    const float* he   = (const float*)d_in[1];
    const float* lnv  = (const float*)d_in[2];
    const float* wq_v = (const float*)d_in[3];
    const float* wk_v = (const float*)d_in[4];
    const float* wv_v = (const float*)d_in[5];
    const float* wo_v = (const float*)d_in[6];
    const float* lne  = (const float*)d_in[7];
    const float* wq_e = (const float*)d_in[8];
    const float* wk_e = (const float*)d_in[9];
    const float* wv_e = (const float*)d_in[10];
    const float* wo_e = (const float*)d_in[11];
    const int*   posv = (const int*)d_in[12];
    const int*   pose = (const int*)d_in[13];
    float* out = (float*)d_out;

    rmsnorm_kernel<<<B_*LT, 256>>>(hv, he, lnv, lne);

    // QKV projections
    gemm_tc<0,0><<<dim3(15,16,4),256>>>(wq_v, nullptr, nullptr, 960, 0,    2048, 0);
    gemm_tc<0,1><<<dim3( 5,16,4),256>>>(wk_v, nullptr, nullptr, 320, 0,    2048, 0);
    gemm_tc<0,2><<<dim3( 5,16,4),256>>>(wv_v, nullptr, nullptr, 320, 0,    2048, 0);
    gemm_tc<0,0><<<dim3(15, 1,4),256>>>(wq_e, nullptr, nullptr, 960, 2048, 64,   0);
    gemm_tc<0,1><<<dim3( 5, 1,4),256>>>(wk_e, nullptr, nullptr, 320, 2048, 64,   0);
    gemm_tc<0,2><<<dim3( 5, 1,4),256>>>(wv_e, nullptr, nullptr, 320, 2048, 64,   0);

    rope_kernel<<<(B_*LT*20)/8, 256>>>(posv, pose);

    attn_tc<<<dim3(17,15,4),256>>>();

    // Output projection + residual, straight into d_out
    gemm_tc<1,3><<<dim3(15,16,4),256>>>(wo_v, out, hv, 960, 0,    2048, 2048);
    gemm_tc<1,3><<<dim3(15, 1,4),256>>>(wo_e, out, he, 960, 2048, 64,   64);
}

// round 6
// speedup vs baseline: 3.0515x; 1.1692x over previous
#include <cuda_runtime.h>
#include <cuda_bf16.h>
#include <math.h>
#include <stdint.h>

// Problem constants
#define B_   4
#define LV   2048
#define LE   64
#define LT   2112      // LV + LE
#define D_   960
#define H_   15
#define KVH_ 5
#define HD_  64
#define NKV  320       // KVH_*HD_

// Scratch (device globals: allocation-free per harness rules)
__device__ float g_xn[B_*LT*D_];     // rmsnormed hidden
__device__ float g_q [B_*LT*D_];     // H*HD, head-major
__device__ float g_k [B_*LT*NKV];
__device__ float g_v [B_*LT*NKV];
__device__ float g_at[B_*LT*D_];     // attention output (head-major)

// ---------------------------------------------------------------------------
// bf16 helpers
// ---------------------------------------------------------------------------
__device__ __forceinline__ uint32_t pack2(float lo, float hi) {
    __nv_bfloat162 h = __floats2bfloat162_rn(lo, hi);  // .x = lo, .y = hi
    return *(uint32_t*)&h;
}
__device__ __forceinline__ void mma16(float* c, const uint32_t* a, uint32_t b0, uint32_t b1) {
    asm("mma.sync.aligned.m16n8k16.row.col.f32.bf16.bf16.f32 "
        "{%0,%1,%2,%3}, {%4,%5,%6,%7}, {%8,%9}, {%0,%1,%2,%3};"
        : "+f"(c[0]), "+f"(c[1]), "+f"(c[2]), "+f"(c[3])
        : "r"(a[0]), "r"(a[1]), "r"(a[2]), "r"(a[3]), "r"(b0), "r"(b1));
}

// ---------------------------------------------------------------------------
// RMSNorm: one block per row -> g_xn
// ---------------------------------------------------------------------------
__global__ void __launch_bounds__(256) rmsnorm_kernel(
    const float* __restrict__ hv, const float* __restrict__ he,
    const float* __restrict__ lnv, const float* __restrict__ lne)
{
    int r = blockIdx.x;
    int b = r / LT, l = r % LT;
    const float* src; const float* w;
    if (l < LV) { src = hv + ((size_t)b*LV + l)*D_; w = lnv; }
    else        { src = he + ((size_t)b*LE + (l-LV))*D_; w = lne; }
    int tid = threadIdx.x;
    float ss = 0.f;
    for (int i = tid; i < D_; i += 256) { float x = src[i]; ss += x*x; }
    #pragma unroll
    for (int o = 16; o > 0; o >>= 1) ss += __shfl_xor_sync(0xffffffffu, ss, o);
    __shared__ float red[8];
    if ((tid & 31) == 0) red[tid >> 5] = ss;
    __syncthreads();
    float tot = 0.f;
    #pragma unroll
    for (int i = 0; i < 8; i++) tot += red[i];
    float inv = rsqrtf(tot * (1.0f/D_) + 1e-6f);
    float* dst = g_xn + (size_t)r * D_;
    for (int i = tid; i < D_; i += 256) dst[i] = src[i] * inv * w[i];
}

// ---------------------------------------------------------------------------
// bf16 tensor-core GEMM (m16n8k16).
//   SRC: 0 = g_xn, 1 = g_at     DST: 0 = g_q, 1 = g_k, 2 = g_v, 3 = Out
// Tile M=128, N=64, Ktile=32 (2 ksteps of 16). 8 warps (4m x 2n), 32x32/warp.
// As [m][k] stride 42 halfs; Ws [n][k] stride 42 halfs (transposed at load).
// ---------------------------------------------------------------------------
#define AS_S 42
#define WS_S 42

template<int SRC, int DST>
__global__ void __launch_bounds__(256) gemm_tc(
    const float* __restrict__ W, float* __restrict__ Out,
    const float* __restrict__ R, int N, int row0, int mvalid, int Rrows)
{
    const float* A = (SRC == 0) ? g_xn : g_at;
    float* C;
    if      (DST == 0) C = g_q;
    else if (DST == 1) C = g_k;
    else if (DST == 2) C = g_v;
    else               C = Out;

    __shared__ __align__(16) __nv_bfloat16 As[128*AS_S];
    __shared__ __align__(16) __nv_bfloat16 Ws[64*WS_S];

    int b  = blockIdx.z;
    int mb = blockIdx.y * 128;
    int n0 = blockIdx.x * 64;
    int tid  = threadIdx.x;
    int wid  = tid >> 5, lane = tid & 31;
    int g = lane >> 2, t = lane & 3;
    int wm = wid >> 1, wn = wid & 1;

    float acc[2][4][4] = {};

    for (int k0 = 0; k0 < D_; k0 += 32) {
        // A tile 128x32 -> bf16 [m][k]
        #pragma unroll
        for (int i = 0; i < 4; i++) {
            int j   = tid + i*256;
            int row = j >> 3;
            int kq  = (j & 7) << 2;
            int rl  = mb + row; if (rl >= mvalid) rl = mvalid - 1;
            float4 v = *(const float4*)(A + ((size_t)(b*LT + row0 + rl))*D_ + k0 + kq);
            *(uint32_t*)&As[row*AS_S + kq    ] = pack2(v.x, v.y);
            *(uint32_t*)&As[row*AS_S + kq + 2] = pack2(v.z, v.w);
        }
        // W tile 32x64 -> bf16 transposed [n][k]
        #pragma unroll
        for (int i = 0; i < 2; i++) {
            int j   = tid + i*256;
            int row = j >> 4;            // k index 0..31
            int c   = (j & 15) << 2;     // n index
            float4 v = *(const float4*)(W + (size_t)(k0 + row)*N + n0 + c);
            Ws[(c+0)*WS_S + row] = __float2bfloat16(v.x);
            Ws[(c+1)*WS_S + row] = __float2bfloat16(v.y);
            Ws[(c+2)*WS_S + row] = __float2bfloat16(v.z);
            Ws[(c+3)*WS_S + row] = __float2bfloat16(v.w);
        }
        __syncthreads();
        #pragma unroll
        for (int ks = 0; ks < 2; ks++) {
            int kb = ks*16;
            uint32_t a[2][4];
            #pragma unroll
            for (int mt = 0; mt < 2; mt++) {
                int rb = wm*32 + mt*16;
                a[mt][0] = *(const uint32_t*)&As[(rb+g  )*AS_S + kb + 2*t    ];
                a[mt][1] = *(const uint32_t*)&As[(rb+g+8)*AS_S + kb + 2*t    ];
                a[mt][2] = *(const uint32_t*)&As[(rb+g  )*AS_S + kb + 2*t + 8];
                a[mt][3] = *(const uint32_t*)&As[(rb+g+8)*AS_S + kb + 2*t + 8];
            }
            #pragma unroll
            for (int nt = 0; nt < 4; nt++) {
                int col = wn*32 + nt*8 + g;
                uint32_t b0 = *(const uint32_t*)&Ws[col*WS_S + kb + 2*t    ];
                uint32_t b1 = *(const uint32_t*)&Ws[col*WS_S + kb + 2*t + 8];
                #pragma unroll
                for (int mt = 0; mt < 2; mt++)
                    mma16(acc[mt][nt], a[mt], b0, b1);
            }
        }
        __syncthreads();
    }

    #pragma unroll
    for (int mt = 0; mt < 2; mt++) {
        #pragma unroll
        for (int nt = 0; nt < 4; nt++) {
            int col = n0 + wn*32 + nt*8 + 2*t;
            int m0r = mb + wm*32 + mt*16 + g;
            if (m0r < mvalid) {
                float2 o = make_float2(acc[mt][nt][0], acc[mt][nt][1]);
                if (R) {
                    float2 rv = *(const float2*)(R + ((size_t)b*Rrows + m0r)*D_ + col);
                    o.x += rv.x; o.y += rv.y;
                }
                *(float2*)(C + ((size_t)(b*LT + row0 + m0r))*N + col) = o;
            }
            int m1r = m0r + 8;
            if (m1r < mvalid) {
                float2 o = make_float2(acc[mt][nt][2], acc[mt][nt][3]);
                if (R) {
                    float2 rv = *(const float2*)(R + ((size_t)b*Rrows + m1r)*D_ + col);
                    o.x += rv.x; o.y += rv.y;
                }
                *(float2*)(C + ((size_t)(b*LT + row0 + m1r))*N + col) = o;
            }
        }
    }
}

// ---------------------------------------------------------------------------
// RoPE in-place on g_q (15 heads) and g_k (5 heads). One warp per (row, head).
// ---------------------------------------------------------------------------
__global__ void __launch_bounds__(256) rope_kernel(
    const int* __restrict__ pos_v, const int* __restrict__ pos_e)
{
    int w    = blockIdx.x * 8 + (threadIdx.x >> 5);
    int lane = threadIdx.x & 31;
    int row = w / 20;
    int hh  = w % 20;
    int b = row / LT, l = row % LT;
    int p = (l < LV) ? pos_v[b*LV + l] : pos_e[b*LE + (l - LV)];
    float ts  = powf(10000.0f, (float)lane * (1.0f/32.0f));
    float rad = (float)p / ts;
    float sn, cs;
    sincosf(rad, &sn, &cs);
    float* base = (hh < H_) ? (g_q + (size_t)row*D_  + hh*HD_)
                            : (g_k + (size_t)row*NKV + (hh - H_)*HD_);
    float x1 = base[lane], x2 = base[lane + 32];
    base[lane]      = x1*cs - x2*sn;
    base[lane + 32] = x2*cs + x1*sn;
}

// ---------------------------------------------------------------------------
// bf16 tensor-core flash attention (m16n8k16).
// Tile 128q x 64k, 8 warps x 16 q rows (warp-local softmax).
// Ks [key][d] stride 66 halfs; Vs [d][key] stride 66 halfs (transposed).
// S C-frag feeds P.V A-frag DIRECTLY (identical layouts) — no shuffles/smem.
// Grid (17 q-tiles, 15 heads, 4 batches); qt 16 = expert rows.
// ---------------------------------------------------------------------------
#define KS_S 66

__global__ void __launch_bounds__(256) attn_tc()
{
    __shared__ __align__(16) __nv_bfloat16 Ks[64*KS_S];
    __shared__ __align__(16) __nv_bfloat16 Vs[64*KS_S];

    int qt = blockIdx.x, h = blockIdx.y, b = blockIdx.z;
    int kvh = h / 3;
    int tid = threadIdx.x;
    int w = tid >> 5, lane = tid & 31;
    int g = lane >> 2, t = lane & 3;
    int q0  = qt * 128;
    int qr0 = w * 16;
    bool is_exp = (qt == 16);
    int nkt = is_exp ? 33 : 32;

    // Q fragments, register resident: 4 k16-steps x 4 half2 regs
    uint32_t qa[4][4];
    {
        int r0 = q0 + qr0 + g;     if (r0 > LT-1) r0 = LT-1;
        int r1 = q0 + qr0 + g + 8; if (r1 > LT-1) r1 = LT-1;
        const float* p0 = g_q + ((size_t)(b*LT + r0))*D_ + h*HD_;
        const float* p1 = g_q + ((size_t)(b*LT + r1))*D_ + h*HD_;
        #pragma unroll
        for (int ks = 0; ks < 4; ks++) {
            int kb = ks*16;
            float2 q00 = *(const float2*)(p0 + kb + 2*t);
            float2 q10 = *(const float2*)(p1 + kb + 2*t);
            float2 q01 = *(const float2*)(p0 + kb + 2*t + 8);
            float2 q11 = *(const float2*)(p1 + kb + 2*t + 8);
            qa[ks][0] = pack2(q00.x*0.125f, q00.y*0.125f);
            qa[ks][1] = pack2(q10.x*0.125f, q10.y*0.125f);
            qa[ks][2] = pack2(q01.x*0.125f, q01.y*0.125f);
            qa[ks][3] = pack2(q11.x*0.125f, q11.y*0.125f);
        }
    }

    float o[8][4] = {};
    float m2[2] = {-1e30f, -1e30f};
    float l2[2] = {0.f, 0.f};

    for (int kt = 0; kt < nkt; kt++) {
        // cooperative load: K natural [key][d] (half2), V transposed [d][key]
        #pragma unroll
        for (int i = 0; i < 4; i++) {
            int j   = tid + i*256;
            int key = j >> 4;
            int dq  = (j & 15) << 2;
            size_t off = ((size_t)(b*LT + kt*64 + key))*NKV + kvh*HD_ + dq;
            float4 kk = *(const float4*)(g_k + off);
            *(uint32_t*)&Ks[key*KS_S + dq    ] = pack2(kk.x, kk.y);
            *(uint32_t*)&Ks[key*KS_S + dq + 2] = pack2(kk.z, kk.w);
            float4 vv = *(const float4*)(g_v + off);
            Vs[(dq+0)*KS_S + key] = __float2bfloat16(vv.x);
            Vs[(dq+1)*KS_S + key] = __float2bfloat16(vv.y);
            Vs[(dq+2)*KS_S + key] = __float2bfloat16(vv.z);
            Vs[(dq+3)*KS_S + key] = __float2bfloat16(vv.w);
        }
        __syncthreads();

        // S = Q K^T  (16q x 64k per warp): B[k=d][n=key] pairs from Ks rows.
        float sacc[8][4] = {};
        #pragma unroll
        for (int ks = 0; ks < 4; ks++) {
            int kb = ks*16;
            #pragma unroll
            for (int nt = 0; nt < 8; nt++) {
                int col = nt*8 + g;
                uint32_t b0 = *(const uint32_t*)&Ks[col*KS_S + kb + 2*t    ];
                uint32_t b1 = *(const uint32_t*)&Ks[col*KS_S + kb + 2*t + 8];
                mma16(sacc[nt], qa[ks], b0, b1);
            }
        }
        // causal mask in expert/expert block
        if (is_exp && kt == 32) {
            int qe0 = qr0 + g, qe1 = qe0 + 8;
            #pragma unroll
            for (int nt = 0; nt < 8; nt++) {
                int c0 = nt*8 + 2*t, c1 = c0 + 1;
                if (c0 > qe0) sacc[nt][0] = -1e30f;
                if (c1 > qe0) sacc[nt][1] = -1e30f;
                if (c0 > qe1) sacc[nt][2] = -1e30f;
                if (c1 > qe1) sacc[nt][3] = -1e30f;
            }
        }
        // online softmax per row-half (rows g and g+8)
        #pragma unroll
        for (int hh = 0; hh < 2; hh++) {
            float rm = -1e30f;
            #pragma unroll
            for (int nt = 0; nt < 8; nt++)
                rm = fmaxf(rm, fmaxf(sacc[nt][hh*2], sacc[nt][hh*2+1]));
            rm = fmaxf(rm, __shfl_xor_sync(0xffffffffu, rm, 1));
            rm = fmaxf(rm, __shfl_xor_sync(0xffffffffu, rm, 2));
            float mn = fmaxf(m2[hh], rm);
            float alpha = __expf(m2[hh] - mn);
            float sum = 0.f;
            #pragma unroll
            for (int nt = 0; nt < 8; nt++) {
                float p0 = __expf(sacc[nt][hh*2  ] - mn);
                float p1 = __expf(sacc[nt][hh*2+1] - mn);
                sacc[nt][hh*2] = p0; sacc[nt][hh*2+1] = p1;
                sum += p0 + p1;
            }
            sum += __shfl_xor_sync(0xffffffffu, sum, 1);
            sum += __shfl_xor_sync(0xffffffffu, sum, 2);
            l2[hh] = l2[hh]*alpha + sum;
            m2[hh] = mn;
            #pragma unroll
            for (int nt = 0; nt < 8; nt++) {
                o[nt][hh*2]   *= alpha;
                o[nt][hh*2+1] *= alpha;
            }
        }
        // O += P V : P A-frag = packed S C-frag (identical layout, no shuffle)
        #pragma unroll
        for (int ks = 0; ks < 4; ks++) {
            int kb = ks*16;
            uint32_t pa[4];
            pa[0] = pack2(sacc[2*ks  ][0], sacc[2*ks  ][1]);
            pa[1] = pack2(sacc[2*ks  ][2], sacc[2*ks  ][3]);
            pa[2] = pack2(sacc[2*ks+1][0], sacc[2*ks+1][1]);
            pa[3] = pack2(sacc[2*ks+1][2], sacc[2*ks+1][3]);
            #pragma unroll
            for (int nt = 0; nt < 8; nt++) {
                int col = nt*8 + g;
                uint32_t b0 = *(const uint32_t*)&Vs[col*KS_S + kb + 2*t    ];
                uint32_t b1 = *(const uint32_t*)&Vs[col*KS_S + kb + 2*t + 8];
                mma16(o[nt], pa, b0, b1);
            }
        }
        __syncthreads();
    }

    // normalize + store
    float inv0 = 1.0f / l2[0];
    float inv1 = 1.0f / l2[1];
    int r0 = q0 + qr0 + g;
    int r1 = r0 + 8;
    #pragma unroll
    for (int nt = 0; nt < 8; nt++) {
        int col = h*HD_ + nt*8 + 2*t;
        if (r0 < LT) {
            float2 ov = make_float2(o[nt][0]*inv0, o[nt][1]*inv0);
            *(float2*)(g_at + ((size_t)(b*LT + r0))*D_ + col) = ov;
        }
        if (r1 < LT) {
            float2 ov = make_float2(o[nt][2]*inv1, o[nt][3]*inv1);
            *(float2*)(g_at + ((size_t)(b*LT + r1))*D_ + col) = ov;
        }
    }
}

// ---------------------------------------------------------------------------
// kernel_launch: ONLY kernel launches (graph-capture friendly).
// ---------------------------------------------------------------------------
extern "C" void kernel_launch(void* const* d_in, const int* in_sizes, int n_in,
                              void* d_out, int out_size)
{
    const float* hv   = (const float*)d_in[0];
    const float* he   = (const float*)d_in[1];
    const float* lnv  = (const float*)d_in[2];
    const float* wq_v = (const float*)d_in[3];
    const float* wk_v = (const float*)d_in[4];
    const float* wv_v = (const float*)d_in[5];
    const float* wo_v = (const float*)d_in[6];
    const float* lne  = (const float*)d_in[7];
    const float* wq_e = (const float*)d_in[8];
    const float* wk_e = (const float*)d_in[9];
    const float* wv_e = (const float*)d_in[10];
    const float* wo_e = (const float*)d_in[11];
    const int*   posv = (const int*)d_in[12];
    const int*   pose = (const int*)d_in[13];
    float* out = (float*)d_out;

    rmsnorm_kernel<<<B_*LT, 256>>>(hv, he, lnv, lne);

    // QKV projections
    gemm_tc<0,0><<<dim3(15,16,4),256>>>(wq_v, nullptr, nullptr, 960, 0,    2048, 0);
    gemm_tc<0,1><<<dim3( 5,16,4),256>>>(wk_v, nullptr, nullptr, 320, 0,    2048, 0);
    gemm_tc<0,2><<<dim3( 5,16,4),256>>>(wv_v, nullptr, nullptr, 320, 0,    2048, 0);
    gemm_tc<0,0><<<dim3(15, 1,4),256>>>(wq_e, nullptr, nullptr, 960, 2048, 64,   0);
    gemm_tc<0,1><<<dim3( 5, 1,4),256>>>(wk_e, nullptr, nullptr, 320, 2048, 64,   0);
    gemm_tc<0,2><<<dim3( 5, 1,4),256>>>(wv_e, nullptr, nullptr, 320, 2048, 64,   0);

    rope_kernel<<<(B_*LT*20)/8, 256>>>(posv, pose);

    attn_tc<<<dim3(17,15,4),256>>>();

    // Output projection + residual, straight into d_out
    gemm_tc<1,3><<<dim3(15,16,4),256>>>(wo_v, out, hv, 960, 0,    2048, 2048);
    gemm_tc<1,3><<<dim3(15, 1,4),256>>>(wo_e, out, he, 960, 2048, 64,   64);
}

// round 8
// speedup vs baseline: 6.0621x; 1.9866x over previous
#include <cuda_runtime.h>
#include <cuda_bf16.h>
#include <math.h>
#include <stdint.h>

// Problem constants
#define B_   4
#define LV   2048
#define LE   64
#define LT   2112      // LV + LE
#define D_   960
#define H_   15
#define KVH_ 5
#define HD_  64
#define NKV  320       // KVH_*HD_

// Scratch (device globals; bf16 activations)
__device__ __nv_bfloat16 g_xn[B_*LT*D_];
__device__ __nv_bfloat16 g_q [B_*LT*D_];
__device__ __nv_bfloat16 g_k [B_*LT*NKV];
__device__ __nv_bfloat16 g_v [B_*LT*NKV];
__device__ __nv_bfloat16 g_at[B_*LT*D_];
// bf16 transposed weights [n][k], k stride 960
__device__ __nv_bfloat16 g_wq_v[960*960];
__device__ __nv_bfloat16 g_wk_v[320*960];
__device__ __nv_bfloat16 g_wv_v[320*960];
__device__ __nv_bfloat16 g_wo_v[960*960];
__device__ __nv_bfloat16 g_wq_e[960*960];
__device__ __nv_bfloat16 g_wk_e[320*960];
__device__ __nv_bfloat16 g_wv_e[320*960];
__device__ __nv_bfloat16 g_wo_e[960*960];

template<int WSEL> __device__ __forceinline__ __nv_bfloat16* wsel() {
    if      (WSEL == 0) return g_wq_v;
    else if (WSEL == 1) return g_wk_v;
    else if (WSEL == 2) return g_wv_v;
    else if (WSEL == 3) return g_wo_v;
    else if (WSEL == 4) return g_wq_e;
    else if (WSEL == 5) return g_wk_e;
    else if (WSEL == 6) return g_wv_e;
    else                return g_wo_e;
}

// ---------------------------------------------------------------------------
// helpers
// ---------------------------------------------------------------------------
__device__ __forceinline__ uint32_t pack2(float lo, float hi) {
    __nv_bfloat162 h = __floats2bfloat162_rn(lo, hi);
    return *(uint32_t*)&h;
}
__device__ __forceinline__ void mma16(float* c, const uint32_t* a, uint32_t b0, uint32_t b1) {
    asm("mma.sync.aligned.m16n8k16.row.col.f32.bf16.bf16.f32 "
        "{%0,%1,%2,%3}, {%4,%5,%6,%7}, {%8,%9}, {%0,%1,%2,%3};"
        : "+f"(c[0]), "+f"(c[1]), "+f"(c[2]), "+f"(c[3])
        : "r"(a[0]), "r"(a[1]), "r"(a[2]), "r"(a[3]), "r"(b0), "r"(b1));
}
__device__ __forceinline__ void ldsm4(uint32_t* r, const __nv_bfloat16* p) {
    uint32_t a = (uint32_t)__cvta_generic_to_shared(p);
    asm volatile("ldmatrix.sync.aligned.m8n8.x4.shared.b16 {%0,%1,%2,%3}, [%4];"
        : "=r"(r[0]), "=r"(r[1]), "=r"(r[2]), "=r"(r[3]) : "r"(a));
}
__device__ __forceinline__ void ldsm4t(uint32_t* r, const __nv_bfloat16* p) {
    uint32_t a = (uint32_t)__cvta_generic_to_shared(p);
    asm volatile("ldmatrix.sync.aligned.m8n8.x4.trans.shared.b16 {%0,%1,%2,%3}, [%4];"
        : "=r"(r[0]), "=r"(r[1]), "=r"(r[2]), "=r"(r[3]) : "r"(a));
}

// ---------------------------------------------------------------------------
// Weight convert + transpose: W[k][n] fp32 -> Wt[n][k] bf16 (k stride 960)
// REQUIRES block = 256 threads.
// ---------------------------------------------------------------------------
template<int WSEL>
__global__ void __launch_bounds__(256) wconv(const float* __restrict__ W, int N)
{
    __shared__ float t[32][33];
    __nv_bfloat16* Wt = wsel<WSEL>();
    int n0 = blockIdx.x * 32, k0 = blockIdx.y * 32;
    int x = threadIdx.x & 31, y = threadIdx.x >> 5;
    #pragma unroll
    for (int i = 0; i < 32; i += 8)
        t[y+i][x] = W[(size_t)(k0+y+i)*N + n0 + x];
    __syncthreads();
    #pragma unroll
    for (int i = 0; i < 32; i += 8)
        Wt[(size_t)(n0+y+i)*960 + k0 + x] = __float2bfloat16(t[x][y+i]);
}

// ---------------------------------------------------------------------------
// RMSNorm: one block per row -> g_xn (bf16)
// ---------------------------------------------------------------------------
__global__ void __launch_bounds__(256) rmsnorm_kernel(
    const float* __restrict__ hv, const float* __restrict__ he,
    const float* __restrict__ lnv, const float* __restrict__ lne)
{
    int r = blockIdx.x;
    int b = r / LT, l = r % LT;
    const float* src; const float* w;
    if (l < LV) { src = hv + ((size_t)b*LV + l)*D_; w = lnv; }
    else        { src = he + ((size_t)b*LE + (l-LV))*D_; w = lne; }
    int tid = threadIdx.x;
    float ss = 0.f;
    for (int i = tid; i < D_; i += 256) { float x = src[i]; ss += x*x; }
    #pragma unroll
    for (int o = 16; o > 0; o >>= 1) ss += __shfl_xor_sync(0xffffffffu, ss, o);
    __shared__ float red[8];
    if ((tid & 31) == 0) red[tid >> 5] = ss;
    __syncthreads();
    float tot = 0.f;
    #pragma unroll
    for (int i = 0; i < 8; i++) tot += red[i];
    float inv = rsqrtf(tot * (1.0f/D_) + 1e-6f);
    __nv_bfloat16* dst = g_xn + (size_t)r * D_;
    for (int i = tid; i < D_; i += 256) dst[i] = __float2bfloat16(src[i] * inv * w[i]);
}

// ---------------------------------------------------------------------------
// bf16 GEMM (m16n8k16 + ldmatrix).
//   SRC: 0 = g_xn, 1 = g_at   DST: 0=g_q, 1=g_k, 2=g_v, 3=Out(fp32+residual)
// Tile M=128, N=64, Ktile=32. 8 warps (4m x 2n), 32x32/warp.
// As[m][k] stride 40 halfs; Ws[n][k] stride 40 halfs.
// ---------------------------------------------------------------------------
#define TS 40

template<int SRC, int DST, int WSEL>
__global__ void __launch_bounds__(256) gemm_tc(
    float* __restrict__ Out, const float* __restrict__ R,
    int N, int row0, int mvalid, int Rrows)
{
    const __nv_bfloat16* A = (SRC == 0) ? g_xn : g_at;
    const __nv_bfloat16* Wt = wsel<WSEL>();
    __nv_bfloat16* Cb;
    if      (DST == 0) Cb = g_q;
    else if (DST == 1) Cb = g_k;
    else               Cb = g_v;

    __shared__ __align__(16) __nv_bfloat16 As[128*TS];
    __shared__ __align__(16) __nv_bfloat16 Ws[64*TS];

    int b  = blockIdx.z;
    int mb = blockIdx.y * 128;
    int n0 = blockIdx.x * 64;
    int tid  = threadIdx.x;
    int wid  = tid >> 5, lane = tid & 31;
    int g = lane >> 2, t = lane & 3;
    int wm = wid >> 1, wn = wid & 1;
    int lr = lane & 7, lb1 = (lane >> 3) & 1, lb2 = lane >> 4;

    float acc[2][4][4] = {};

    for (int k0 = 0; k0 < D_; k0 += 32) {
        // A tile 128x32 halfs: 512 x 16B, 2 per thread
        #pragma unroll
        for (int i = 0; i < 2; i++) {
            int idx = tid + i*256;
            int m = idx >> 2, seg = idx & 3;
            int rl = mb + m; if (rl >= mvalid) rl = mvalid - 1;
            *(uint4*)&As[m*TS + seg*8] =
                *(const uint4*)(A + ((size_t)(b*LT + row0 + rl))*D_ + k0 + seg*8);
        }
        // W tile 64x32 halfs: 256 x 16B
        {
            int n = tid >> 2, seg = tid & 3;
            *(uint4*)&Ws[n*TS + seg*8] =
                *(const uint4*)(Wt + (size_t)(n0 + n)*960 + k0 + seg*8);
        }
        __syncthreads();
        #pragma unroll
        for (int ks = 0; ks < 2; ks++) {
            int kb = ks*16;
            uint32_t a[2][4];
            #pragma unroll
            for (int mt = 0; mt < 2; mt++)
                ldsm4(a[mt], &As[(wm*32 + mt*16 + lr + lb1*8)*TS + kb + lb2*8]);
            #pragma unroll
            for (int ntp = 0; ntp < 2; ntp++) {
                uint32_t bq[4];
                ldsm4(bq, &Ws[(wn*32 + ntp*16 + lr + lb2*8)*TS + kb + lb1*8]);
                #pragma unroll
                for (int mt = 0; mt < 2; mt++) {
                    mma16(acc[mt][2*ntp  ], a[mt], bq[0], bq[1]);
                    mma16(acc[mt][2*ntp+1], a[mt], bq[2], bq[3]);
                }
            }
        }
        __syncthreads();
    }

    #pragma unroll
    for (int mt = 0; mt < 2; mt++) {
        #pragma unroll
        for (int nt = 0; nt < 4; nt++) {
            int col = n0 + wn*32 + nt*8 + 2*t;
            int m0r = mb + wm*32 + mt*16 + g;
            int m1r = m0r + 8;
            if (DST == 3) {
                if (m0r < mvalid) {
                    float2 rv = *(const float2*)(R + ((size_t)b*Rrows + m0r)*D_ + col);
                    float2 o = make_float2(acc[mt][nt][0] + rv.x, acc[mt][nt][1] + rv.y);
                    *(float2*)(Out + ((size_t)(b*LT + row0 + m0r))*N + col) = o;
                }
                if (m1r < mvalid) {
                    float2 rv = *(const float2*)(R + ((size_t)b*Rrows + m1r)*D_ + col);
                    float2 o = make_float2(acc[mt][nt][2] + rv.x, acc[mt][nt][3] + rv.y);
                    *(float2*)(Out + ((size_t)(b*LT + row0 + m1r))*N + col) = o;
                }
            } else {
                if (m0r < mvalid)
                    *(uint32_t*)&Cb[((size_t)(b*LT + row0 + m0r))*N + col] =
                        pack2(acc[mt][nt][0], acc[mt][nt][1]);
                if (m1r < mvalid)
                    *(uint32_t*)&Cb[((size_t)(b*LT + row0 + m1r))*N + col] =
                        pack2(acc[mt][nt][2], acc[mt][nt][3]);
            }
        }
    }
}

// ---------------------------------------------------------------------------
// RoPE in-place on bf16 g_q (15 heads, folds 0.125 scale) and g_k (5 heads).
// ---------------------------------------------------------------------------
__global__ void __launch_bounds__(256) rope_kernel(
    const int* __restrict__ pos_v, const int* __restrict__ pos_e)
{
    int w    = blockIdx.x * 8 + (threadIdx.x >> 5);
    int lane = threadIdx.x & 31;
    int row = w / 20;
    int hh  = w % 20;
    int b = row / LT, l = row % LT;
    int p = (l < LV) ? pos_v[b*LV + l] : pos_e[b*LE + (l - LV)];
    float ts  = powf(10000.0f, (float)lane * (1.0f/32.0f));
    float rad = (float)p / ts;
    float sn, cs;
    sincosf(rad, &sn, &cs);
    bool isq = (hh < H_);
    __nv_bfloat16* base = isq ? (g_q + (size_t)row*D_  + hh*HD_)
                              : (g_k + (size_t)row*NKV + (hh - H_)*HD_);
    float x1 = __bfloat162float(base[lane]);
    float x2 = __bfloat162float(base[lane + 32]);
    float sc = isq ? 0.125f : 1.0f;
    base[lane]      = __float2bfloat16((x1*cs - x2*sn) * sc);
    base[lane + 32] = __float2bfloat16((x2*cs + x1*sn) * sc);
}

// ---------------------------------------------------------------------------
// bf16 flash attention (m16n8k16 + ldmatrix, V via ldmatrix.trans).
// Tile 128q x 64k, 8 warps x 16 q rows. K,V natural [key][d], stride 72 halfs.
// Grid (17, 15, 4); qt 16 = expert rows (causal over expert keys).
// ---------------------------------------------------------------------------
#define KS 72

__global__ void __launch_bounds__(256) attn_tc()
{
    __shared__ __align__(16) __nv_bfloat16 Ksm[64*KS];
    __shared__ __align__(16) __nv_bfloat16 Vsm[64*KS];

    int qt = blockIdx.x, h = blockIdx.y, b = blockIdx.z;
    int kvh = h / 3;
    int tid = threadIdx.x;
    int w = tid >> 5, lane = tid & 31;
    int g = lane >> 2, t = lane & 3;
    int lr = lane & 7, lb1 = (lane >> 3) & 1, lb2 = lane >> 4;
    int q0  = qt * 128;
    int qr0 = w * 16;
    bool is_exp = (qt == 16);
    int nkt = is_exp ? 33 : 32;

    // Q fragments (pre-scaled by rope): 4 k16-steps x 4 pair regs
    uint32_t qa[4][4];
    {
        int r0 = q0 + qr0 + g;     if (r0 > LT-1) r0 = LT-1;
        int r1 = q0 + qr0 + g + 8; if (r1 > LT-1) r1 = LT-1;
        const __nv_bfloat16* p0 = g_q + ((size_t)(b*LT + r0))*D_ + h*HD_;
        const __nv_bfloat16* p1 = g_q + ((size_t)(b*LT + r1))*D_ + h*HD_;
        #pragma unroll
        for (int ks = 0; ks < 4; ks++) {
            int kb = ks*16;
            qa[ks][0] = *(const uint32_t*)(p0 + kb + 2*t);
            qa[ks][1] = *(const uint32_t*)(p1 + kb + 2*t);
            qa[ks][2] = *(const uint32_t*)(p0 + kb + 2*t + 8);
            qa[ks][3] = *(const uint32_t*)(p1 + kb + 2*t + 8);
        }
    }

    float o[8][4] = {};
    float m2[2] = {-1e30f, -1e30f};
    float l2[2] = {0.f, 0.f};

    for (int kt = 0; kt < nkt; kt++) {
        // load K,V tiles: 64 keys x 64 d halfs = 512 x 16B each
        #pragma unroll
        for (int i = 0; i < 2; i++) {
            int idx = tid + i*256;
            int key = idx >> 3, seg = idx & 7;
            size_t off = ((size_t)(b*LT + kt*64 + key))*NKV + kvh*HD_ + seg*8;
            *(uint4*)&Ksm[key*KS + seg*8] = *(const uint4*)(g_k + off);
            *(uint4*)&Vsm[key*KS + seg*8] = *(const uint4*)(g_v + off);
        }
        __syncthreads();

        // S = Q K^T (16q x 64k per warp)
        float sacc[8][4] = {};
        #pragma unroll
        for (int ks = 0; ks < 4; ks++) {
            int kb = ks*16;
            #pragma unroll
            for (int ntp = 0; ntp < 4; ntp++) {
                uint32_t bq[4];
                ldsm4(bq, &Ksm[(ntp*16 + lr + lb2*8)*KS + kb + lb1*8]);
                mma16(sacc[2*ntp  ], qa[ks], bq[0], bq[1]);
                mma16(sacc[2*ntp+1], qa[ks], bq[2], bq[3]);
            }
        }
        // causal mask in expert/expert block
        if (is_exp && kt == 32) {
            int qe0 = qr0 + g, qe1 = qe0 + 8;
            #pragma unroll
            for (int nt = 0; nt < 8; nt++) {
                int c0 = nt*8 + 2*t, c1 = c0 + 1;
                if (c0 > qe0) sacc[nt][0] = -1e30f;
                if (c1 > qe0) sacc[nt][1] = -1e30f;
                if (c0 > qe1) sacc[nt][2] = -1e30f;
                if (c1 > qe1) sacc[nt][3] = -1e30f;
            }
        }
        // online softmax per row-half (rows g and g+8)
        #pragma unroll
        for (int hh = 0; hh < 2; hh++) {
            float rm = -1e30f;
            #pragma unroll
            for (int nt = 0; nt < 8; nt++)
                rm = fmaxf(rm, fmaxf(sacc[nt][hh*2], sacc[nt][hh*2+1]));
            rm = fmaxf(rm, __shfl_xor_sync(0xffffffffu, rm, 1));
            rm = fmaxf(rm, __shfl_xor_sync(0xffffffffu, rm, 2));
            float mn = fmaxf(m2[hh], rm);
            float alpha = __expf(m2[hh] - mn);
            float sum = 0.f;
            #pragma unroll
            for (int nt = 0; nt < 8; nt++) {
                float p0 = __expf(sacc[nt][hh*2  ] - mn);
                float p1 = __expf(sacc[nt][hh*2+1] - mn);
                sacc[nt][hh*2] = p0; sacc[nt][hh*2+1] = p1;
                sum += p0 + p1;
            }
            sum += __shfl_xor_sync(0xffffffffu, sum, 1);
            sum += __shfl_xor_sync(0xffffffffu, sum, 2);
            l2[hh] = l2[hh]*alpha + sum;
            m2[hh] = mn;
            #pragma unroll
            for (int nt = 0; nt < 8; nt++) {
                o[nt][hh*2]   *= alpha;
                o[nt][hh*2+1] *= alpha;
            }
        }
        // O += P V (P A-frag packed straight from S C-frag; V via LDSM.trans)
        #pragma unroll
        for (int ks = 0; ks < 4; ks++) {
            int kb = ks*16;
            uint32_t pa[4];
            pa[0] = pack2(sacc[2*ks  ][0], sacc[2*ks  ][1]);
            pa[1] = pack2(sacc[2*ks  ][2], sacc[2*ks  ][3]);
            pa[2] = pack2(sacc[2*ks+1][0], sacc[2*ks+1][1]);
            pa[3] = pack2(sacc[2*ks+1][2], sacc[2*ks+1][3]);
            #pragma unroll
            for (int ntp = 0; ntp < 4; ntp++) {
                uint32_t bq[4];
                ldsm4t(bq, &Vsm[(kb + lr + lb1*8)*KS + ntp*16 + lb2*8]);
                mma16(o[2*ntp  ], pa, bq[0], bq[1]);
                mma16(o[2*ntp+1], pa, bq[2], bq[3]);
            }
        }
        __syncthreads();
    }

    // normalize + store bf16
    float inv0 = 1.0f / l2[0];
    float inv1 = 1.0f / l2[1];
    int r0 = q0 + qr0 + g;
    int r1 = r0 + 8;
    #pragma unroll
    for (int nt = 0; nt < 8; nt++) {
        int col = h*HD_ + nt*8 + 2*t;
        if (r0 < LT)
            *(uint32_t*)&g_at[((size_t)(b*LT + r0))*D_ + col] =
                pack2(o[nt][0]*inv0, o[nt][1]*inv0);
        if (r1 < LT)
            *(uint32_t*)&g_at[((size_t)(b*LT + r1))*D_ + col] =
                pack2(o[nt][2]*inv1, o[nt][3]*inv1);
    }
}

// ---------------------------------------------------------------------------
// kernel_launch: ONLY kernel launches (graph-capture friendly).
// ---------------------------------------------------------------------------
extern "C" void kernel_launch(void* const* d_in, const int* in_sizes, int n_in,
                              void* d_out, int out_size)
{
    const float* hv   = (const float*)d_in[0];
    const float* he   = (const float*)d_in[1];
    const float* lnv  = (const float*)d_in[2];
    const float* wq_v = (const float*)d_in[3];
    const float* wk_v = (const float*)d_in[4];
    const float* wv_v = (const float*)d_in[5];
    const float* wo_v = (const float*)d_in[6];
    const float* lne  = (const float*)d_in[7];
    const float* wq_e = (const float*)d_in[8];
    const float* wk_e = (const float*)d_in[9];
    const float* wv_e = (const float*)d_in[10];
    const float* wo_e = (const float*)d_in[11];
    const int*   posv = (const int*)d_in[12];
    const int*   pose = (const int*)d_in[13];
    float* out = (float*)d_out;

    // weight convert+transpose to bf16 [n][k]  (block = 256 REQUIRED)
    wconv<0><<<dim3(30,30), 256>>>(wq_v, 960);
    wconv<1><<<dim3(10,30), 256>>>(wk_v, 320);
    wconv<2><<<dim3(10,30), 256>>>(wv_v, 320);
    wconv<3><<<dim3(30,30), 256>>>(wo_v, 960);
    wconv<4><<<dim3(30,30), 256>>>(wq_e, 960);
    wconv<5><<<dim3(10,30), 256>>>(wk_e, 320);
    wconv<6><<<dim3(10,30), 256>>>(wv_e, 320);
    wconv<7><<<dim3(30,30), 256>>>(wo_e, 960);

    rmsnorm_kernel<<<B_*LT, 256>>>(hv, he, lnv, lne);

    // QKV projections
    gemm_tc<0,0,0><<<dim3(15,16,4),256>>>(nullptr, nullptr, 960, 0,    2048, 0);
    gemm_tc<0,1,1><<<dim3( 5,16,4),256>>>(nullptr, nullptr, 320, 0,    2048, 0);
    gemm_tc<0,2,2><<<dim3( 5,16,4),256>>>(nullptr, nullptr, 320, 0,    2048, 0);
    gemm_tc<0,0,4><<<dim3(15, 1,4),256>>>(nullptr, nullptr, 960, 2048, 64,   0);
    gemm_tc<0,1,5><<<dim3( 5, 1,4),256>>>(nullptr, nullptr, 320, 2048, 64,   0);
    gemm_tc<0,2,6><<<dim3( 5, 1,4),256>>>(nullptr, nullptr, 320, 2048, 64,   0);

    rope_kernel<<<(B_*LT*20)/8, 256>>>(posv, pose);

    attn_tc<<<dim3(17,15,4),256>>>();

    // Output projection + residual, straight into d_out
    gemm_tc<1,3,3><<<dim3(15,16,4),256>>>(out, hv, 960, 0,    2048, 2048);
    gemm_tc<1,3,7><<<dim3(15, 1,4),256>>>(out, he, 960, 2048, 64,   64);
}

// round 9
// speedup vs baseline: 6.6913x; 1.1038x over previous
#include <cuda_runtime.h>
#include <cuda_bf16.h>
#include <math.h>
#include <stdint.h>

// Problem constants
#define B_   4
#define LV   2048
#define LE   64
#define LT   2112      // LV + LE
#define D_   960
#define H_   15
#define KVH_ 5
#define HD_  64
#define NKV  320       // KVH_*HD_

// Scratch (device globals; bf16 activations)
__device__ __nv_bfloat16 g_xn[B_*LT*D_];
__device__ __nv_bfloat16 g_q [B_*LT*D_];
__device__ __nv_bfloat16 g_k [B_*LT*NKV];
__device__ __nv_bfloat16 g_v [B_*LT*NKV];
__device__ __nv_bfloat16 g_at[B_*LT*D_];
// bf16 transposed weights [n][k], k stride 960
__device__ __nv_bfloat16 g_wq_v[960*960];
__device__ __nv_bfloat16 g_wk_v[320*960];
__device__ __nv_bfloat16 g_wv_v[320*960];
__device__ __nv_bfloat16 g_wo_v[960*960];
__device__ __nv_bfloat16 g_wq_e[960*960];
__device__ __nv_bfloat16 g_wk_e[320*960];
__device__ __nv_bfloat16 g_wv_e[320*960];
__device__ __nv_bfloat16 g_wo_e[960*960];

template<int WSEL> __device__ __forceinline__ __nv_bfloat16* wsel() {
    if      (WSEL == 0) return g_wq_v;
    else if (WSEL == 1) return g_wk_v;
    else if (WSEL == 2) return g_wv_v;
    else if (WSEL == 3) return g_wo_v;
    else if (WSEL == 4) return g_wq_e;
    else if (WSEL == 5) return g_wk_e;
    else if (WSEL == 6) return g_wv_e;
    else                return g_wo_e;
}

// ---------------------------------------------------------------------------
// helpers
// ---------------------------------------------------------------------------
__device__ __forceinline__ uint32_t pack2(float lo, float hi) {
    __nv_bfloat162 h = __floats2bfloat162_rn(lo, hi);
    return *(uint32_t*)&h;
}
__device__ __forceinline__ void mma16(float* c, const uint32_t* a, uint32_t b0, uint32_t b1) {
    asm("mma.sync.aligned.m16n8k16.row.col.f32.bf16.bf16.f32 "
        "{%0,%1,%2,%3}, {%4,%5,%6,%7}, {%8,%9}, {%0,%1,%2,%3};"
        : "+f"(c[0]), "+f"(c[1]), "+f"(c[2]), "+f"(c[3])
        : "r"(a[0]), "r"(a[1]), "r"(a[2]), "r"(a[3]), "r"(b0), "r"(b1));
}
__device__ __forceinline__ void ldsm4(uint32_t* r, const __nv_bfloat16* p) {
    uint32_t a = (uint32_t)__cvta_generic_to_shared(p);
    asm volatile("ldmatrix.sync.aligned.m8n8.x4.shared.b16 {%0,%1,%2,%3}, [%4];"
        : "=r"(r[0]), "=r"(r[1]), "=r"(r[2]), "=r"(r[3]) : "r"(a));
}
__device__ __forceinline__ void ldsm4t(uint32_t* r, const __nv_bfloat16* p) {
    uint32_t a = (uint32_t)__cvta_generic_to_shared(p);
    asm volatile("ldmatrix.sync.aligned.m8n8.x4.trans.shared.b16 {%0,%1,%2,%3}, [%4];"
        : "=r"(r[0]), "=r"(r[1]), "=r"(r[2]), "=r"(r[3]) : "r"(a));
}
__device__ __forceinline__ void cp16(__nv_bfloat16* smem, const __nv_bfloat16* gmem) {
    uint32_t a = (uint32_t)__cvta_generic_to_shared(smem);
    asm volatile("cp.async.cg.shared.global [%0], [%1], 16;" :: "r"(a), "l"(gmem));
}
__device__ __forceinline__ void cp_commit() { asm volatile("cp.async.commit_group;"); }
__device__ __forceinline__ void cp_wait1()  { asm volatile("cp.async.wait_group 1;"); }
__device__ __forceinline__ void cp_wait0()  { asm volatile("cp.async.wait_group 0;"); }

// ---------------------------------------------------------------------------
// Fused weight convert + transpose for all 8 weights.
// W[k][n] fp32 -> Wt[n][k] bf16 (k stride 960). Block = 256. Grid (30,30,8).
// ---------------------------------------------------------------------------
__global__ void __launch_bounds__(256) wconv_all(
    const float* w0, const float* w1, const float* w2, const float* w3,
    const float* w4, const float* w5, const float* w6, const float* w7)
{
    int sel = blockIdx.z;
    const float* W; __nv_bfloat16* Wt; int N;
    if      (sel == 0) { W = w0; Wt = g_wq_v; N = 960; }
    else if (sel == 1) { W = w1; Wt = g_wk_v; N = 320; }
    else if (sel == 2) { W = w2; Wt = g_wv_v; N = 320; }
    else if (sel == 3) { W = w3; Wt = g_wo_v; N = 960; }
    else if (sel == 4) { W = w4; Wt = g_wq_e; N = 960; }
    else if (sel == 5) { W = w5; Wt = g_wk_e; N = 320; }
    else if (sel == 6) { W = w6; Wt = g_wv_e; N = 320; }
    else               { W = w7; Wt = g_wo_e; N = 960; }
    int n0 = blockIdx.x * 32, k0 = blockIdx.y * 32;
    if (n0 >= N) return;
    __shared__ float t[32][33];
    int x = threadIdx.x & 31, y = threadIdx.x >> 5;
    #pragma unroll
    for (int i = 0; i < 32; i += 8)
        t[y+i][x] = W[(size_t)(k0+y+i)*N + n0 + x];
    __syncthreads();
    #pragma unroll
    for (int i = 0; i < 32; i += 8)
        Wt[(size_t)(n0+y+i)*960 + k0 + x] = __float2bfloat16(t[x][y+i]);
}

// ---------------------------------------------------------------------------
// RMSNorm: one block per row -> g_xn (bf16)
// ---------------------------------------------------------------------------
__global__ void __launch_bounds__(256) rmsnorm_kernel(
    const float* __restrict__ hv, const float* __restrict__ he,
    const float* __restrict__ lnv, const float* __restrict__ lne)
{
    int r = blockIdx.x;
    int b = r / LT, l = r % LT;
    const float* src; const float* w;
    if (l < LV) { src = hv + ((size_t)b*LV + l)*D_; w = lnv; }
    else        { src = he + ((size_t)b*LE + (l-LV))*D_; w = lne; }
    int tid = threadIdx.x;
    float ss = 0.f;
    for (int i = tid; i < D_; i += 256) { float x = src[i]; ss += x*x; }
    #pragma unroll
    for (int o = 16; o > 0; o >>= 1) ss += __shfl_xor_sync(0xffffffffu, ss, o);
    __shared__ float red[8];
    if ((tid & 31) == 0) red[tid >> 5] = ss;
    __syncthreads();
    float tot = 0.f;
    #pragma unroll
    for (int i = 0; i < 8; i++) tot += red[i];
    float inv = rsqrtf(tot * (1.0f/D_) + 1e-6f);
    __nv_bfloat16* dst = g_xn + (size_t)r * D_;
    for (int i = tid; i < D_; i += 256) dst[i] = __float2bfloat16(src[i] * inv * w[i]);
}

// ---------------------------------------------------------------------------
// bf16 GEMM (m16n8k16 + ldmatrix + cp.async double buffering).
//   SRC: 0 = g_xn, 1 = g_at   DST: 0=g_q, 1=g_k, 2=g_v, 3=Out(fp32+residual)
// Tile M=128, N=64, Ktile=32, 30 k-tiles. 8 warps (4m x 2n), 32x32/warp.
// ---------------------------------------------------------------------------
#define TS 40
#define NKT_GEMM 30

template<int SRC, int DST, int WSEL>
__global__ void __launch_bounds__(256) gemm_tc(
    float* __restrict__ Out, const float* __restrict__ R,
    int N, int row0, int mvalid, int Rrows)
{
    const __nv_bfloat16* A = (SRC == 0) ? g_xn : g_at;
    const __nv_bfloat16* Wt = wsel<WSEL>();
    __nv_bfloat16* Cb;
    if      (DST == 0) Cb = g_q;
    else if (DST == 1) Cb = g_k;
    else               Cb = g_v;

    __shared__ __align__(16) __nv_bfloat16 As[2][128*TS];
    __shared__ __align__(16) __nv_bfloat16 Ws[2][64*TS];

    int b  = blockIdx.z;
    int mb = blockIdx.y * 128;
    int n0 = blockIdx.x * 64;
    int tid  = threadIdx.x;
    int wid  = tid >> 5, lane = tid & 31;
    int g = lane >> 2, t = lane & 3;
    int wm = wid >> 1, wn = wid & 1;
    int lr = lane & 7, lb1 = (lane >> 3) & 1, lb2 = lane >> 4;

    // per-thread load coords (hoisted)
    int am0 = tid >> 2,        aseg0 = (tid & 3);
    int am1 = (tid+256) >> 2,  aseg1 = ((tid+256) & 3);
    int rl0 = mb + am0; if (rl0 >= mvalid) rl0 = mvalid - 1;
    int rl1 = mb + am1; if (rl1 >= mvalid) rl1 = mvalid - 1;
    const __nv_bfloat16* a_src0 = A + ((size_t)(b*LT + row0 + rl0))*D_ + aseg0*8;
    const __nv_bfloat16* a_src1 = A + ((size_t)(b*LT + row0 + rl1))*D_ + aseg1*8;
    int wn_ = tid >> 2, wseg = tid & 3;
    const __nv_bfloat16* w_src = Wt + (size_t)(n0 + wn_)*960 + wseg*8;

    float acc[2][4][4] = {};

    // prologue: prefetch tile 0
    {
        cp16(&As[0][am0*TS + aseg0*8], a_src0);
        cp16(&As[0][am1*TS + aseg1*8], a_src1);
        cp16(&Ws[0][wn_*TS + wseg*8], w_src);
        cp_commit();
    }

    for (int it = 0; it < NKT_GEMM; it++) {
        int buf = it & 1;
        if (it + 1 < NKT_GEMM) {
            int k0 = (it+1)*32;
            cp16(&As[buf^1][am0*TS + aseg0*8], a_src0 + k0);
            cp16(&As[buf^1][am1*TS + aseg1*8], a_src1 + k0);
            cp16(&Ws[buf^1][wn_*TS + wseg*8], w_src + k0);
            cp_commit();
            cp_wait1();
        } else {
            cp_wait0();
        }
        __syncthreads();

        #pragma unroll
        for (int ks = 0; ks < 2; ks++) {
            int kb = ks*16;
            uint32_t a[2][4];
            #pragma unroll
            for (int mt = 0; mt < 2; mt++)
                ldsm4(a[mt], &As[buf][(wm*32 + mt*16 + lr + lb1*8)*TS + kb + lb2*8]);
            #pragma unroll
            for (int ntp = 0; ntp < 2; ntp++) {
                uint32_t bq[4];
                ldsm4(bq, &Ws[buf][(wn*32 + ntp*16 + lr + lb2*8)*TS + kb + lb1*8]);
                #pragma unroll
                for (int mt = 0; mt < 2; mt++) {
                    mma16(acc[mt][2*ntp  ], a[mt], bq[0], bq[1]);
                    mma16(acc[mt][2*ntp+1], a[mt], bq[2], bq[3]);
                }
            }
        }
        __syncthreads();
    }

    #pragma unroll
    for (int mt = 0; mt < 2; mt++) {
        #pragma unroll
        for (int nt = 0; nt < 4; nt++) {
            int col = n0 + wn*32 + nt*8 + 2*t;
            int m0r = mb + wm*32 + mt*16 + g;
            int m1r = m0r + 8;
            if (DST == 3) {
                if (m0r < mvalid) {
                    float2 rv = *(const float2*)(R + ((size_t)b*Rrows + m0r)*D_ + col);
                    float2 o = make_float2(acc[mt][nt][0] + rv.x, acc[mt][nt][1] + rv.y);
                    *(float2*)(Out + ((size_t)(b*LT + row0 + m0r))*N + col) = o;
                }
                if (m1r < mvalid) {
                    float2 rv = *(const float2*)(R + ((size_t)b*Rrows + m1r)*D_ + col);
                    float2 o = make_float2(acc[mt][nt][2] + rv.x, acc[mt][nt][3] + rv.y);
                    *(float2*)(Out + ((size_t)(b*LT + row0 + m1r))*N + col) = o;
                }
            } else {
                if (m0r < mvalid)
                    *(uint32_t*)&Cb[((size_t)(b*LT + row0 + m0r))*N + col] =
                        pack2(acc[mt][nt][0], acc[mt][nt][1]);
                if (m1r < mvalid)
                    *(uint32_t*)&Cb[((size_t)(b*LT + row0 + m1r))*N + col] =
                        pack2(acc[mt][nt][2], acc[mt][nt][3]);
            }
        }
    }
}

// ---------------------------------------------------------------------------
// RoPE in-place on bf16 g_q (15 heads, folds 0.125 scale) and g_k (5 heads).
// ---------------------------------------------------------------------------
__global__ void __launch_bounds__(256) rope_kernel(
    const int* __restrict__ pos_v, const int* __restrict__ pos_e)
{
    int w    = blockIdx.x * 8 + (threadIdx.x >> 5);
    int lane = threadIdx.x & 31;
    int row = w / 20;
    int hh  = w % 20;
    int b = row / LT, l = row % LT;
    int p = (l < LV) ? pos_v[b*LV + l] : pos_e[b*LE + (l - LV)];
    float ts  = powf(10000.0f, (float)lane * (1.0f/32.0f));
    float rad = (float)p / ts;
    float sn, cs;
    sincosf(rad, &sn, &cs);
    bool isq = (hh < H_);
    __nv_bfloat16* base = isq ? (g_q + (size_t)row*D_  + hh*HD_)
                              : (g_k + (size_t)row*NKV + (hh - H_)*HD_);
    float x1 = __bfloat162float(base[lane]);
    float x2 = __bfloat162float(base[lane + 32]);
    float sc = isq ? 0.125f : 1.0f;
    base[lane]      = __float2bfloat16((x1*cs - x2*sn) * sc);
    base[lane + 32] = __float2bfloat16((x2*cs + x1*sn) * sc);
}

// ---------------------------------------------------------------------------
// bf16 flash attention (m16n8k16 + ldmatrix + cp.async double buffering).
// Tile 128q x 64k, 8 warps x 16 q rows. K,V natural [key][d], stride 72 halfs.
// Grid (17, 15, 4); qt 16 = expert rows (causal over expert keys).
// ---------------------------------------------------------------------------
#define KS 72

__global__ void __launch_bounds__(256) attn_tc()
{
    __shared__ __align__(16) __nv_bfloat16 Ksm[2][64*KS];
    __shared__ __align__(16) __nv_bfloat16 Vsm[2][64*KS];

    int qt = blockIdx.x, h = blockIdx.y, b = blockIdx.z;
    int kvh = h / 3;
    int tid = threadIdx.x;
    int w = tid >> 5, lane = tid & 31;
    int g = lane >> 2, t = lane & 3;
    int lr = lane & 7, lb1 = (lane >> 3) & 1, lb2 = lane >> 4;
    int q0  = qt * 128;
    int qr0 = w * 16;
    bool is_exp = (qt == 16);
    int nkt = is_exp ? 33 : 32;

    // per-thread KV load coords (hoisted): 2 chunks per array
    int key0 = tid >> 3,        seg0 = (tid & 7);
    int key1 = (tid+256) >> 3,  seg1 = ((tid+256) & 7);
    const __nv_bfloat16* k_src0 = g_k + ((size_t)(b*LT + key0))*NKV + kvh*HD_ + seg0*8;
    const __nv_bfloat16* k_src1 = g_k + ((size_t)(b*LT + key1))*NKV + kvh*HD_ + seg1*8;
    const __nv_bfloat16* v_src0 = g_v + ((size_t)(b*LT + key0))*NKV + kvh*HD_ + seg0*8;
    const __nv_bfloat16* v_src1 = g_v + ((size_t)(b*LT + key1))*NKV + kvh*HD_ + seg1*8;

    // Q fragments (pre-scaled by rope): 4 k16-steps x 4 pair regs
    uint32_t qa[4][4];
    {
        int r0 = q0 + qr0 + g;     if (r0 > LT-1) r0 = LT-1;
        int r1 = q0 + qr0 + g + 8; if (r1 > LT-1) r1 = LT-1;
        const __nv_bfloat16* p0 = g_q + ((size_t)(b*LT + r0))*D_ + h*HD_;
        const __nv_bfloat16* p1 = g_q + ((size_t)(b*LT + r1))*D_ + h*HD_;
        #pragma unroll
        for (int ks = 0; ks < 4; ks++) {
            int kb = ks*16;
            qa[ks][0] = *(const uint32_t*)(p0 + kb + 2*t);
            qa[ks][1] = *(const uint32_t*)(p1 + kb + 2*t);
            qa[ks][2] = *(const uint32_t*)(p0 + kb + 2*t + 8);
            qa[ks][3] = *(const uint32_t*)(p1 + kb + 2*t + 8);
        }
    }

    float o[8][4] = {};
    float m2[2] = {-1e30f, -1e30f};
    float l2[2] = {0.f, 0.f};

    // prologue: prefetch kv-tile 0
    {
        cp16(&Ksm[0][key0*KS + seg0*8], k_src0);
        cp16(&Ksm[0][key1*KS + seg1*8], k_src1);
        cp16(&Vsm[0][key0*KS + seg0*8], v_src0);
        cp16(&Vsm[0][key1*KS + seg1*8], v_src1);
        cp_commit();
    }

    for (int kt = 0; kt < nkt; kt++) {
        int buf = kt & 1;
        if (kt + 1 < nkt) {
            size_t off = (size_t)(kt+1)*64*NKV;
            cp16(&Ksm[buf^1][key0*KS + seg0*8], k_src0 + off);
            cp16(&Ksm[buf^1][key1*KS + seg1*8], k_src1 + off);
            cp16(&Vsm[buf^1][key0*KS + seg0*8], v_src0 + off);
            cp16(&Vsm[buf^1][key1*KS + seg1*8], v_src1 + off);
            cp_commit();
            cp_wait1();
        } else {
            cp_wait0();
        }
        __syncthreads();

        // S = Q K^T (16q x 64k per warp)
        float sacc[8][4] = {};
        #pragma unroll
        for (int ks = 0; ks < 4; ks++) {
            int kb = ks*16;
            #pragma unroll
            for (int ntp = 0; ntp < 4; ntp++) {
                uint32_t bq[4];
                ldsm4(bq, &Ksm[buf][(ntp*16 + lr + lb2*8)*KS + kb + lb1*8]);
                mma16(sacc[2*ntp  ], qa[ks], bq[0], bq[1]);
                mma16(sacc[2*ntp+1], qa[ks], bq[2], bq[3]);
            }
        }
        // causal mask in expert/expert block
        if (is_exp && kt == 32) {
            int qe0 = qr0 + g, qe1 = qe0 + 8;
            #pragma unroll
            for (int nt = 0; nt < 8; nt++) {
                int c0 = nt*8 + 2*t, c1 = c0 + 1;
                if (c0 > qe0) sacc[nt][0] = -1e30f;
                if (c1 > qe0) sacc[nt][1] = -1e30f;
                if (c0 > qe1) sacc[nt][2] = -1e30f;
                if (c1 > qe1) sacc[nt][3] = -1e30f;
            }
        }
        // online softmax per row-half (rows g and g+8)
        #pragma unroll
        for (int hh = 0; hh < 2; hh++) {
            float rm = -1e30f;
            #pragma unroll
            for (int nt = 0; nt < 8; nt++)
                rm = fmaxf(rm, fmaxf(sacc[nt][hh*2], sacc[nt][hh*2+1]));
            rm = fmaxf(rm, __shfl_xor_sync(0xffffffffu, rm, 1));
            rm = fmaxf(rm, __shfl_xor_sync(0xffffffffu, rm, 2));
            float mn = fmaxf(m2[hh], rm);
            float alpha = __expf(m2[hh] - mn);
            float sum = 0.f;
            #pragma unroll
            for (int nt = 0; nt < 8; nt++) {
                float p0 = __expf(sacc[nt][hh*2  ] - mn);
                float p1 = __expf(sacc[nt][hh*2+1] - mn);
                sacc[nt][hh*2] = p0; sacc[nt][hh*2+1] = p1;
                sum += p0 + p1;
            }
            sum += __shfl_xor_sync(0xffffffffu, sum, 1);
            sum += __shfl_xor_sync(0xffffffffu, sum, 2);
            l2[hh] = l2[hh]*alpha + sum;
            m2[hh] = mn;
            #pragma unroll
            for (int nt = 0; nt < 8; nt++) {
                o[nt][hh*2]   *= alpha;
                o[nt][hh*2+1] *= alpha;
            }
        }
        // O += P V (P A-frag packed straight from S C-frag; V via LDSM.trans)
        #pragma unroll
        for (int ks = 0; ks < 4; ks++) {
            int kb = ks*16;
            uint32_t pa[4];
            pa[0] = pack2(sacc[2*ks  ][0], sacc[2*ks  ][1]);
            pa[1] = pack2(sacc[2*ks  ][2], sacc[2*ks  ][3]);
            pa[2] = pack2(sacc[2*ks+1][0], sacc[2*ks+1][1]);
            pa[3] = pack2(sacc[2*ks+1][2], sacc[2*ks+1][3]);
            #pragma unroll
            for (int ntp = 0; ntp < 4; ntp++) {
                uint32_t bq[4];
                ldsm4t(bq, &Vsm[buf][(kb + lr + lb1*8)*KS + ntp*16 + lb2*8]);
                mma16(o[2*ntp  ], pa, bq[0], bq[1]);
                mma16(o[2*ntp+1], pa, bq[2], bq[3]);
            }
        }
        __syncthreads();
    }

    // normalize + store bf16
    float inv0 = 1.0f / l2[0];
    float inv1 = 1.0f / l2[1];
    int r0 = q0 + qr0 + g;
    int r1 = r0 + 8;
    #pragma unroll
    for (int nt = 0; nt < 8; nt++) {
        int col = h*HD_ + nt*8 + 2*t;
        if (r0 < LT)
            *(uint32_t*)&g_at[((size_t)(b*LT + r0))*D_ + col] =
                pack2(o[nt][0]*inv0, o[nt][1]*inv0);
        if (r1 < LT)
            *(uint32_t*)&g_at[((size_t)(b*LT + r1))*D_ + col] =
                pack2(o[nt][2]*inv1, o[nt][3]*inv1);
    }
}

// ---------------------------------------------------------------------------
// kernel_launch: ONLY kernel launches (graph-capture friendly).
// ---------------------------------------------------------------------------
extern "C" void kernel_launch(void* const* d_in, const int* in_sizes, int n_in,
                              void* d_out, int out_size)
{
    const float* hv   = (const float*)d_in[0];
    const float* he   = (const float*)d_in[1];
    const float* lnv  = (const float*)d_in[2];
    const float* wq_v = (const float*)d_in[3];
    const float* wk_v = (const float*)d_in[4];
    const float* wv_v = (const float*)d_in[5];
    const float* wo_v = (const float*)d_in[6];
    const float* lne  = (const float*)d_in[7];
    const float* wq_e = (const float*)d_in[8];
    const float* wk_e = (const float*)d_in[9];
    const float* wv_e = (const float*)d_in[10];
    const float* wo_e = (const float*)d_in[11];
    const int*   posv = (const int*)d_in[12];
    const int*   pose = (const int*)d_in[13];
    float* out = (float*)d_out;

    // fused weight convert+transpose to bf16 [n][k]
    wconv_all<<<dim3(30,30,8), 256>>>(wq_v, wk_v, wv_v, wo_v, wq_e, wk_e, wv_e, wo_e);

    rmsnorm_kernel<<<B_*LT, 256>>>(hv, he, lnv, lne);

    // QKV projections
    gemm_tc<0,0,0><<<dim3(15,16,4),256>>>(nullptr, nullptr, 960, 0,    2048, 0);
    gemm_tc<0,1,1><<<dim3( 5,16,4),256>>>(nullptr, nullptr, 320, 0,    2048, 0);
    gemm_tc<0,2,2><<<dim3( 5,16,4),256>>>(nullptr, nullptr, 320, 0,    2048, 0);
    gemm_tc<0,0,4><<<dim3(15, 1,4),256>>>(nullptr, nullptr, 960, 2048, 64,   0);
    gemm_tc<0,1,5><<<dim3( 5, 1,4),256>>>(nullptr, nullptr, 320, 2048, 64,   0);
    gemm_tc<0,2,6><<<dim3( 5, 1,4),256>>>(nullptr, nullptr, 320, 2048, 64,   0);

    rope_kernel<<<(B_*LT*20)/8, 256>>>(posv, pose);

    attn_tc<<<dim3(17,15,4),256>>>();

    // Output projection + residual, straight into d_out
    gemm_tc<1,3,3><<<dim3(15,16,4),256>>>(out, hv, 960, 0,    2048, 2048);
    gemm_tc<1,3,7><<<dim3(15, 1,4),256>>>(out, he, 960, 2048, 64,   64);
}

// round 10
// speedup vs baseline: 8.1622x; 1.2198x over previous
#include <cuda_runtime.h>
#include <cuda_bf16.h>
#include <math.h>
#include <stdint.h>

// Problem constants
#define B_   4
#define LV   2048
#define LE   64
#define LT   2112      // LV + LE
#define D_   960
#define H_   15
#define KVH_ 5
#define HD_  64
#define NKV  320       // KVH_*HD_

// Scratch (device globals; bf16 activations)
__device__ __nv_bfloat16 g_xn[B_*LT*D_];
__device__ __nv_bfloat16 g_q [B_*LT*D_];
__device__ __nv_bfloat16 g_k [B_*LT*NKV];
__device__ __nv_bfloat16 g_v [B_*LT*NKV];
__device__ __nv_bfloat16 g_at[B_*LT*D_];
// bf16 transposed weights [n][k], k stride 960
__device__ __nv_bfloat16 g_wq_v[960*960];
__device__ __nv_bfloat16 g_wk_v[320*960];
__device__ __nv_bfloat16 g_wv_v[320*960];
__device__ __nv_bfloat16 g_wo_v[960*960];
__device__ __nv_bfloat16 g_wq_e[960*960];
__device__ __nv_bfloat16 g_wk_e[320*960];
__device__ __nv_bfloat16 g_wv_e[320*960];
__device__ __nv_bfloat16 g_wo_e[960*960];

// ---------------------------------------------------------------------------
// helpers
// ---------------------------------------------------------------------------
__device__ __forceinline__ uint32_t pack2(float lo, float hi) {
    __nv_bfloat162 h = __floats2bfloat162_rn(lo, hi);
    return *(uint32_t*)&h;
}
__device__ __forceinline__ void mma16(float* c, const uint32_t* a, uint32_t b0, uint32_t b1) {
    asm("mma.sync.aligned.m16n8k16.row.col.f32.bf16.bf16.f32 "
        "{%0,%1,%2,%3}, {%4,%5,%6,%7}, {%8,%9}, {%0,%1,%2,%3};"
        : "+f"(c[0]), "+f"(c[1]), "+f"(c[2]), "+f"(c[3])
        : "r"(a[0]), "r"(a[1]), "r"(a[2]), "r"(a[3]), "r"(b0), "r"(b1));
}
__device__ __forceinline__ void ldsm4(uint32_t* r, const __nv_bfloat16* p) {
    uint32_t a = (uint32_t)__cvta_generic_to_shared(p);
    asm volatile("ldmatrix.sync.aligned.m8n8.x4.shared.b16 {%0,%1,%2,%3}, [%4];"
        : "=r"(r[0]), "=r"(r[1]), "=r"(r[2]), "=r"(r[3]) : "r"(a));
}
__device__ __forceinline__ void ldsm4t(uint32_t* r, const __nv_bfloat16* p) {
    uint32_t a = (uint32_t)__cvta_generic_to_shared(p);
    asm volatile("ldmatrix.sync.aligned.m8n8.x4.trans.shared.b16 {%0,%1,%2,%3}, [%4];"
        : "=r"(r[0]), "=r"(r[1]), "=r"(r[2]), "=r"(r[3]) : "r"(a));
}
__device__ __forceinline__ void cp16(__nv_bfloat16* smem, const __nv_bfloat16* gmem) {
    uint32_t a = (uint32_t)__cvta_generic_to_shared(smem);
    asm volatile("cp.async.cg.shared.global [%0], [%1], 16;" :: "r"(a), "l"(gmem));
}
__device__ __forceinline__ void cp_commit() { asm volatile("cp.async.commit_group;"); }
__device__ __forceinline__ void cp_wait1()  { asm volatile("cp.async.wait_group 1;"); }
__device__ __forceinline__ void cp_wait0()  { asm volatile("cp.async.wait_group 0;"); }

// ---------------------------------------------------------------------------
// Fused weight convert + transpose for all 8 weights.
// W[k][n] fp32 -> Wt[n][k] bf16 (k stride 960). Block = 256. Grid (30,30,8).
// ---------------------------------------------------------------------------
__global__ void __launch_bounds__(256) wconv_all(
    const float* w0, const float* w1, const float* w2, const float* w3,
    const float* w4, const float* w5, const float* w6, const float* w7)
{
    int sel = blockIdx.z;
    const float* W; __nv_bfloat16* Wt; int N;
    if      (sel == 0) { W = w0; Wt = g_wq_v; N = 960; }
    else if (sel == 1) { W = w1; Wt = g_wk_v; N = 320; }
    else if (sel == 2) { W = w2; Wt = g_wv_v; N = 320; }
    else if (sel == 3) { W = w3; Wt = g_wo_v; N = 960; }
    else if (sel == 4) { W = w4; Wt = g_wq_e; N = 960; }
    else if (sel == 5) { W = w5; Wt = g_wk_e; N = 320; }
    else if (sel == 6) { W = w6; Wt = g_wv_e; N = 320; }
    else               { W = w7; Wt = g_wo_e; N = 960; }
    int n0 = blockIdx.x * 32, k0 = blockIdx.y * 32;
    if (n0 >= N) return;
    __shared__ float t[32][33];
    int x = threadIdx.x & 31, y = threadIdx.x >> 5;
    #pragma unroll
    for (int i = 0; i < 32; i += 8)
        t[y+i][x] = W[(size_t)(k0+y+i)*N + n0 + x];
    __syncthreads();
    #pragma unroll
    for (int i = 0; i < 32; i += 8)
        Wt[(size_t)(n0+y+i)*960 + k0 + x] = __float2bfloat16(t[x][y+i]);
}

// ---------------------------------------------------------------------------
// RMSNorm: one block per row -> g_xn (bf16)
// ---------------------------------------------------------------------------
__global__ void __launch_bounds__(256) rmsnorm_kernel(
    const float* __restrict__ hv, const float* __restrict__ he,
    const float* __restrict__ lnv, const float* __restrict__ lne)
{
    int r = blockIdx.x;
    int b = r / LT, l = r % LT;
    const float* src; const float* w;
    if (l < LV) { src = hv + ((size_t)b*LV + l)*D_; w = lnv; }
    else        { src = he + ((size_t)b*LE + (l-LV))*D_; w = lne; }
    int tid = threadIdx.x;
    float ss = 0.f;
    for (int i = tid; i < D_; i += 256) { float x = src[i]; ss += x*x; }
    #pragma unroll
    for (int o = 16; o > 0; o >>= 1) ss += __shfl_xor_sync(0xffffffffu, ss, o);
    __shared__ float red[8];
    if ((tid & 31) == 0) red[tid >> 5] = ss;
    __syncthreads();
    float tot = 0.f;
    #pragma unroll
    for (int i = 0; i < 8; i++) tot += red[i];
    float inv = rsqrtf(tot * (1.0f/D_) + 1e-6f);
    __nv_bfloat16* dst = g_xn + (size_t)r * D_;
    for (int i = tid; i < D_; i += 256) dst[i] = __float2bfloat16(src[i] * inv * w[i]);
}

// ---------------------------------------------------------------------------
// Fused bf16 GEMM, 3-stage cp.async ring, ONE syncthreads per k-iter.
// MODE 0: QKV. grid (25, 17, 4). n-tile: [0,15)=Q, [15,20)=K, [20,25)=V.
//         m-tile 16 = expert stream (row0=2048, *_e weights), else VLM.
// MODE 1: O-proj. grid (15, 17, 4). fp32 out + residual (hv / he).
// Tile M=128, N=64, Ktile=32, 30 k-tiles. 8 warps (4m x 2n), 32x32/warp.
// ---------------------------------------------------------------------------
#define TS 40
#define NKT_GEMM 30

template<int MODE>
__global__ void __launch_bounds__(256) fgemm(
    float* __restrict__ Out, const float* __restrict__ Rv, const float* __restrict__ Re)
{
    __shared__ __align__(16) __nv_bfloat16 As[3][128*TS];
    __shared__ __align__(16) __nv_bfloat16 Ws[3][64*TS];

    int nx = blockIdx.x;
    int my = blockIdx.y;
    int b  = blockIdx.z;
    bool is_exp = (my == 16);
    int row0   = is_exp ? 2048 : 0;
    int mb     = is_exp ? 0    : my*128;
    int mvalid = is_exp ? 64   : 2048;

    const __nv_bfloat16* A;
    const __nv_bfloat16* Wt;
    __nv_bfloat16* Cb = nullptr;
    const float* R = nullptr;
    int N, n0, Rrows = 0;
    if (MODE == 0) {
        A = g_xn;
        if (nx < 15)      { Wt = is_exp ? g_wq_e : g_wq_v; Cb = g_q; N = 960; n0 = nx*64; }
        else if (nx < 20) { Wt = is_exp ? g_wk_e : g_wk_v; Cb = g_k; N = 320; n0 = (nx-15)*64; }
        else              { Wt = is_exp ? g_wv_e : g_wv_v; Cb = g_v; N = 320; n0 = (nx-20)*64; }
    } else {
        A = g_at;
        Wt = is_exp ? g_wo_e : g_wo_v;
        R  = is_exp ? Re : Rv;
        Rrows = is_exp ? 64 : 2048;
        N = 960; n0 = nx*64;
    }

    int tid  = threadIdx.x;
    int wid  = tid >> 5, lane = tid & 31;
    int g = lane >> 2, t = lane & 3;
    int wm = wid >> 1, wn = wid & 1;
    int lr = lane & 7, lb1 = (lane >> 3) & 1, lb2 = lane >> 4;

    // per-thread load coords (hoisted)
    int am0 = tid >> 2,        aseg0 = (tid & 3);
    int am1 = (tid+256) >> 2,  aseg1 = ((tid+256) & 3);
    int rl0 = mb + am0; if (rl0 >= mvalid) rl0 = mvalid - 1;
    int rl1 = mb + am1; if (rl1 >= mvalid) rl1 = mvalid - 1;
    const __nv_bfloat16* a_src0 = A + ((size_t)(b*LT + row0 + rl0))*D_ + aseg0*8;
    const __nv_bfloat16* a_src1 = A + ((size_t)(b*LT + row0 + rl1))*D_ + aseg1*8;
    int wn_ = tid >> 2, wseg = tid & 3;
    const __nv_bfloat16* w_src = Wt + (size_t)(n0 + wn_)*960 + wseg*8;

    float acc[2][4][4] = {};

    // prologue: prefetch stages 0 and 1
    {
        cp16(&As[0][am0*TS + aseg0*8], a_src0);
        cp16(&As[0][am1*TS + aseg1*8], a_src1);
        cp16(&Ws[0][wn_*TS + wseg*8], w_src);
        cp_commit();
        cp16(&As[1][am0*TS + aseg0*8], a_src0 + 32);
        cp16(&As[1][am1*TS + aseg1*8], a_src1 + 32);
        cp16(&Ws[1][wn_*TS + wseg*8], w_src + 32);
        cp_commit();
    }

    int s = 0;       // stage of iteration it
    int ps = 2;      // stage to prefetch (it+2)
    for (int it = 0; it < NKT_GEMM; it++) {
        if (it < NKT_GEMM - 2) cp_wait1(); else cp_wait0();
        __syncthreads();
        if (it + 2 < NKT_GEMM) {
            int k0 = (it+2)*32;
            cp16(&As[ps][am0*TS + aseg0*8], a_src0 + k0);
            cp16(&As[ps][am1*TS + aseg1*8], a_src1 + k0);
            cp16(&Ws[ps][wn_*TS + wseg*8], w_src + k0);
            cp_commit();
        }

        #pragma unroll
        for (int ks = 0; ks < 2; ks++) {
            int kb = ks*16;
            uint32_t a[2][4];
            #pragma unroll
            for (int mt = 0; mt < 2; mt++)
                ldsm4(a[mt], &As[s][(wm*32 + mt*16 + lr + lb1*8)*TS + kb + lb2*8]);
            #pragma unroll
            for (int ntp = 0; ntp < 2; ntp++) {
                uint32_t bq[4];
                ldsm4(bq, &Ws[s][(wn*32 + ntp*16 + lr + lb2*8)*TS + kb + lb1*8]);
                #pragma unroll
                for (int mt = 0; mt < 2; mt++) {
                    mma16(acc[mt][2*ntp  ], a[mt], bq[0], bq[1]);
                    mma16(acc[mt][2*ntp+1], a[mt], bq[2], bq[3]);
                }
            }
        }
        s  = (s  == 2) ? 0 : s + 1;
        ps = (ps == 2) ? 0 : ps + 1;
    }

    #pragma unroll
    for (int mt = 0; mt < 2; mt++) {
        #pragma unroll
        for (int nt = 0; nt < 4; nt++) {
            int col = n0 + wn*32 + nt*8 + 2*t;
            int m0r = mb + wm*32 + mt*16 + g;
            int m1r = m0r + 8;
            if (MODE == 1) {
                if (m0r < mvalid) {
                    float2 rv = *(const float2*)(R + ((size_t)b*Rrows + m0r)*D_ + col);
                    float2 o = make_float2(acc[mt][nt][0] + rv.x, acc[mt][nt][1] + rv.y);
                    *(float2*)(Out + ((size_t)(b*LT + row0 + m0r))*D_ + col) = o;
                }
                if (m1r < mvalid) {
                    float2 rv = *(const float2*)(R + ((size_t)b*Rrows + m1r)*D_ + col);
                    float2 o = make_float2(acc[mt][nt][2] + rv.x, acc[mt][nt][3] + rv.y);
                    *(float2*)(Out + ((size_t)(b*LT + row0 + m1r))*D_ + col) = o;
                }
            } else {
                if (m0r < mvalid)
                    *(uint32_t*)&Cb[((size_t)(b*LT + row0 + m0r))*N + col] =
                        pack2(acc[mt][nt][0], acc[mt][nt][1]);
                if (m1r < mvalid)
                    *(uint32_t*)&Cb[((size_t)(b*LT + row0 + m1r))*N + col] =
                        pack2(acc[mt][nt][2], acc[mt][nt][3]);
            }
        }
    }
}

// ---------------------------------------------------------------------------
// RoPE in-place on bf16 g_q (15 heads, folds 0.125 scale) and g_k (5 heads).
// ---------------------------------------------------------------------------
__global__ void __launch_bounds__(256) rope_kernel(
    const int* __restrict__ pos_v, const int* __restrict__ pos_e)
{
    int w    = blockIdx.x * 8 + (threadIdx.x >> 5);
    int lane = threadIdx.x & 31;
    int row = w / 20;
    int hh  = w % 20;
    int b = row / LT, l = row % LT;
    int p = (l < LV) ? pos_v[b*LV + l] : pos_e[b*LE + (l - LV)];
    float ts  = powf(10000.0f, (float)lane * (1.0f/32.0f));
    float rad = (float)p / ts;
    float sn, cs;
    sincosf(rad, &sn, &cs);
    bool isq = (hh < H_);
    __nv_bfloat16* base = isq ? (g_q + (size_t)row*D_  + hh*HD_)
                              : (g_k + (size_t)row*NKV + (hh - H_)*HD_);
    float x1 = __bfloat162float(base[lane]);
    float x2 = __bfloat162float(base[lane + 32]);
    float sc = isq ? 0.125f : 1.0f;
    base[lane]      = __float2bfloat16((x1*cs - x2*sn) * sc);
    base[lane + 32] = __float2bfloat16((x2*cs + x1*sn) * sc);
}

// ---------------------------------------------------------------------------
// bf16 flash attention (m16n8k16 + ldmatrix + cp.async double buffering).
// Tile 128q x 64k, 8 warps x 16 q rows. K,V natural [key][d], stride 72 halfs.
// Grid (17, 15, 4); qt 16 = expert rows (causal over expert keys).
// ---------------------------------------------------------------------------
#define KS 72

__global__ void __launch_bounds__(256) attn_tc()
{
    __shared__ __align__(16) __nv_bfloat16 Ksm[2][64*KS];
    __shared__ __align__(16) __nv_bfloat16 Vsm[2][64*KS];

    int qt = blockIdx.x, h = blockIdx.y, b = blockIdx.z;
    int kvh = h / 3;
    int tid = threadIdx.x;
    int w = tid >> 5, lane = tid & 31;
    int g = lane >> 2, t = lane & 3;
    int lr = lane & 7, lb1 = (lane >> 3) & 1, lb2 = lane >> 4;
    int q0  = qt * 128;
    int qr0 = w * 16;
    bool is_exp = (qt == 16);
    int nkt = is_exp ? 33 : 32;

    // per-thread KV load coords (hoisted): 2 chunks per array
    int key0 = tid >> 3,        seg0 = (tid & 7);
    int key1 = (tid+256) >> 3,  seg1 = ((tid+256) & 7);
    const __nv_bfloat16* k_src0 = g_k + ((size_t)(b*LT + key0))*NKV + kvh*HD_ + seg0*8;
    const __nv_bfloat16* k_src1 = g_k + ((size_t)(b*LT + key1))*NKV + kvh*HD_ + seg1*8;
    const __nv_bfloat16* v_src0 = g_v + ((size_t)(b*LT + key0))*NKV + kvh*HD_ + seg0*8;
    const __nv_bfloat16* v_src1 = g_v + ((size_t)(b*LT + key1))*NKV + kvh*HD_ + seg1*8;

    // Q fragments (pre-scaled by rope): 4 k16-steps x 4 pair regs
    uint32_t qa[4][4];
    {
        int r0 = q0 + qr0 + g;     if (r0 > LT-1) r0 = LT-1;
        int r1 = q0 + qr0 + g + 8; if (r1 > LT-1) r1 = LT-1;
        const __nv_bfloat16* p0 = g_q + ((size_t)(b*LT + r0))*D_ + h*HD_;
        const __nv_bfloat16* p1 = g_q + ((size_t)(b*LT + r1))*D_ + h*HD_;
        #pragma unroll
        for (int ks = 0; ks < 4; ks++) {
            int kb = ks*16;
            qa[ks][0] = *(const uint32_t*)(p0 + kb + 2*t);
            qa[ks][1] = *(const uint32_t*)(p1 + kb + 2*t);
            qa[ks][2] = *(const uint32_t*)(p0 + kb + 2*t + 8);
            qa[ks][3] = *(const uint32_t*)(p1 + kb + 2*t + 8);
        }
    }

    float o[8][4] = {};
    float m2[2] = {-1e30f, -1e30f};
    float l2[2] = {0.f, 0.f};

    // prologue: prefetch kv-tile 0
    {
        cp16(&Ksm[0][key0*KS + seg0*8], k_src0);
        cp16(&Ksm[0][key1*KS + seg1*8], k_src1);
        cp16(&Vsm[0][key0*KS + seg0*8], v_src0);
        cp16(&Vsm[0][key1*KS + seg1*8], v_src1);
        cp_commit();
    }

    for (int kt = 0; kt < nkt; kt++) {
        int buf = kt & 1;
        if (kt + 1 < nkt) {
            size_t off = (size_t)(kt+1)*64*NKV;
            cp16(&Ksm[buf^1][key0*KS + seg0*8], k_src0 + off);
            cp16(&Ksm[buf^1][key1*KS + seg1*8], k_src1 + off);
            cp16(&Vsm[buf^1][key0*KS + seg0*8], v_src0 + off);
            cp16(&Vsm[buf^1][key1*KS + seg1*8], v_src1 + off);
            cp_commit();
            cp_wait1();
        } else {
            cp_wait0();
        }
        __syncthreads();

        // S = Q K^T (16q x 64k per warp)
        float sacc[8][4] = {};
        #pragma unroll
        for (int ks = 0; ks < 4; ks++) {
            int kb = ks*16;
            #pragma unroll
            for (int ntp = 0; ntp < 4; ntp++) {
                uint32_t bq[4];
                ldsm4(bq, &Ksm[buf][(ntp*16 + lr + lb2*8)*KS + kb + lb1*8]);
                mma16(sacc[2*ntp  ], qa[ks], bq[0], bq[1]);
                mma16(sacc[2*ntp+1], qa[ks], bq[2], bq[3]);
            }
        }
        // causal mask in expert/expert block
        if (is_exp && kt == 32) {
            int qe0 = qr0 + g, qe1 = qe0 + 8;
            #pragma unroll
            for (int nt = 0; nt < 8; nt++) {
                int c0 = nt*8 + 2*t, c1 = c0 + 1;
                if (c0 > qe0) sacc[nt][0] = -1e30f;
                if (c1 > qe0) sacc[nt][1] = -1e30f;
                if (c0 > qe1) sacc[nt][2] = -1e30f;
                if (c1 > qe1) sacc[nt][3] = -1e30f;
            }
        }
        // online softmax per row-half (rows g and g+8)
        #pragma unroll
        for (int hh = 0; hh < 2; hh++) {
            float rm = -1e30f;
            #pragma unroll
            for (int nt = 0; nt < 8; nt++)
                rm = fmaxf(rm, fmaxf(sacc[nt][hh*2], sacc[nt][hh*2+1]));
            rm = fmaxf(rm, __shfl_xor_sync(0xffffffffu, rm, 1));
            rm = fmaxf(rm, __shfl_xor_sync(0xffffffffu, rm, 2));
            float mn = fmaxf(m2[hh], rm);
            float alpha = __expf(m2[hh] - mn);
            float sum = 0.f;
            #pragma unroll
            for (int nt = 0; nt < 8; nt++) {
                float p0 = __expf(sacc[nt][hh*2  ] - mn);
                float p1 = __expf(sacc[nt][hh*2+1] - mn);
                sacc[nt][hh*2] = p0; sacc[nt][hh*2+1] = p1;
                sum += p0 + p1;
            }
            sum += __shfl_xor_sync(0xffffffffu, sum, 1);
            sum += __shfl_xor_sync(0xffffffffu, sum, 2);
            l2[hh] = l2[hh]*alpha + sum;
            m2[hh] = mn;
            #pragma unroll
            for (int nt = 0; nt < 8; nt++) {
                o[nt][hh*2]   *= alpha;
                o[nt][hh*2+1] *= alpha;
            }
        }
        // O += P V (P A-frag packed straight from S C-frag; V via LDSM.trans)
        #pragma unroll
        for (int ks = 0; ks < 4; ks++) {
            int kb = ks*16;
            uint32_t pa[4];
            pa[0] = pack2(sacc[2*ks  ][0], sacc[2*ks  ][1]);
            pa[1] = pack2(sacc[2*ks  ][2], sacc[2*ks  ][3]);
            pa[2] = pack2(sacc[2*ks+1][0], sacc[2*ks+1][1]);
            pa[3] = pack2(sacc[2*ks+1][2], sacc[2*ks+1][3]);
            #pragma unroll
            for (int ntp = 0; ntp < 4; ntp++) {
                uint32_t bq[4];
                ldsm4t(bq, &Vsm[buf][(kb + lr + lb1*8)*KS + ntp*16 + lb2*8]);
                mma16(o[2*ntp  ], pa, bq[0], bq[1]);
                mma16(o[2*ntp+1], pa, bq[2], bq[3]);
            }
        }
        __syncthreads();
    }

    // normalize + store bf16
    float inv0 = 1.0f / l2[0];
    float inv1 = 1.0f / l2[1];
    int r0 = q0 + qr0 + g;
    int r1 = r0 + 8;
    #pragma unroll
    for (int nt = 0; nt < 8; nt++) {
        int col = h*HD_ + nt*8 + 2*t;
        if (r0 < LT)
            *(uint32_t*)&g_at[((size_t)(b*LT + r0))*D_ + col] =
                pack2(o[nt][0]*inv0, o[nt][1]*inv0);
        if (r1 < LT)
            *(uint32_t*)&g_at[((size_t)(b*LT + r1))*D_ + col] =
                pack2(o[nt][2]*inv1, o[nt][3]*inv1);
    }
}

// ---------------------------------------------------------------------------
// kernel_launch: ONLY kernel launches (graph-capture friendly).
// ---------------------------------------------------------------------------
extern "C" void kernel_launch(void* const* d_in, const int* in_sizes, int n_in,
                              void* d_out, int out_size)
{
    const float* hv   = (const float*)d_in[0];
    const float* he   = (const float*)d_in[1];
    const float* lnv  = (const float*)d_in[2];
    const float* wq_v = (const float*)d_in[3];
    const float* wk_v = (const float*)d_in[4];
    const float* wv_v = (const float*)d_in[5];
    const float* wo_v = (const float*)d_in[6];
    const float* lne  = (const float*)d_in[7];
    const float* wq_e = (const float*)d_in[8];
    const float* wk_e = (const float*)d_in[9];
    const float* wv_e = (const float*)d_in[10];
    const float* wo_e = (const float*)d_in[11];
    const int*   posv = (const int*)d_in[12];
    const int*   pose = (const int*)d_in[13];
    float* out = (float*)d_out;

    // fused weight convert+transpose to bf16 [n][k]
    wconv_all<<<dim3(30,30,8), 256>>>(wq_v, wk_v, wv_v, wo_v, wq_e, wk_e, wv_e, wo_e);

    rmsnorm_kernel<<<B_*LT, 256>>>(hv, he, lnv, lne);

    // fused QKV projection, both streams
    fgemm<0><<<dim3(25,17,4), 256>>>(nullptr, nullptr, nullptr);

    rope_kernel<<<(B_*LT*20)/8, 256>>>(posv, pose);

    attn_tc<<<dim3(17,15,4), 256>>>();

    // fused output projection + residual, both streams
    fgemm<1><<<dim3(15,17,4), 256>>>(out, hv, he);
}

// round 13
// speedup vs baseline: 8.5062x; 1.0421x over previous
#include <cuda_runtime.h>
#include <cuda_bf16.h>
#include <math.h>
#include <stdint.h>

// Problem constants
#define B_   4
#define LV   2048
#define LE   64
#define LT   2112      // LV + LE
#define D_   960
#define H_   15
#define KVH_ 5
#define HD_  64
#define NKV  320       // KVH_*HD_

// Scratch (device globals; bf16 activations)
__device__ __nv_bfloat16 g_xn[B_*LT*D_];
__device__ __nv_bfloat16 g_q [B_*LT*D_];
__device__ __nv_bfloat16 g_k [B_*LT*NKV];
__device__ __nv_bfloat16 g_v [B_*LT*NKV];
__device__ __nv_bfloat16 g_at[B_*LT*D_];
// bf16 transposed weights [n][k], k stride 960
__device__ __nv_bfloat16 g_wq_v[960*960];
__device__ __nv_bfloat16 g_wk_v[320*960];
__device__ __nv_bfloat16 g_wv_v[320*960];
__device__ __nv_bfloat16 g_wo_v[960*960];
__device__ __nv_bfloat16 g_wq_e[960*960];
__device__ __nv_bfloat16 g_wk_e[320*960];
__device__ __nv_bfloat16 g_wv_e[320*960];
__device__ __nv_bfloat16 g_wo_e[960*960];

// ---------------------------------------------------------------------------
// helpers
// ---------------------------------------------------------------------------
__device__ __forceinline__ uint32_t pack2(float lo, float hi) {
    __nv_bfloat162 h = __floats2bfloat162_rn(lo, hi);
    return *(uint32_t*)&h;
}
__device__ __forceinline__ void mma16(float* c, const uint32_t* a, uint32_t b0, uint32_t b1) {
    asm("mma.sync.aligned.m16n8k16.row.col.f32.bf16.bf16.f32 "
        "{%0,%1,%2,%3}, {%4,%5,%6,%7}, {%8,%9}, {%0,%1,%2,%3};"
        : "+f"(c[0]), "+f"(c[1]), "+f"(c[2]), "+f"(c[3])
        : "r"(a[0]), "r"(a[1]), "r"(a[2]), "r"(a[3]), "r"(b0), "r"(b1));
}
__device__ __forceinline__ void ldsm4(uint32_t* r, const __nv_bfloat16* p) {
    uint32_t a = (uint32_t)__cvta_generic_to_shared(p);
    asm volatile("ldmatrix.sync.aligned.m8n8.x4.shared.b16 {%0,%1,%2,%3}, [%4];"
        : "=r"(r[0]), "=r"(r[1]), "=r"(r[2]), "=r"(r[3]) : "r"(a));
}
__device__ __forceinline__ void ldsm4t(uint32_t* r, const __nv_bfloat16* p) {
    uint32_t a = (uint32_t)__cvta_generic_to_shared(p);
    asm volatile("ldmatrix.sync.aligned.m8n8.x4.trans.shared.b16 {%0,%1,%2,%3}, [%4];"
        : "=r"(r[0]), "=r"(r[1]), "=r"(r[2]), "=r"(r[3]) : "r"(a));
}
__device__ __forceinline__ void cp16(__nv_bfloat16* smem, const __nv_bfloat16* gmem) {
    uint32_t a = (uint32_t)__cvta_generic_to_shared(smem);
    asm volatile("cp.async.cg.shared.global [%0], [%1], 16;" :: "r"(a), "l"(gmem));
}
__device__ __forceinline__ void cp_commit() { asm volatile("cp.async.commit_group;"); }
__device__ __forceinline__ void cp_wait1()  { asm volatile("cp.async.wait_group 1;"); }
__device__ __forceinline__ void cp_wait0()  { asm volatile("cp.async.wait_group 0;"); }

// ---------------------------------------------------------------------------
// Fused weight convert + transpose for all 8 weights.
// W[k][n] fp32 -> Wt[n][k] bf16 (k stride 960). Block = 256. Grid (30,30,8).
// ---------------------------------------------------------------------------
__global__ void __launch_bounds__(256) wconv_all(
    const float* w0, const float* w1, const float* w2, const float* w3,
    const float* w4, const float* w5, const float* w6, const float* w7)
{
    int sel = blockIdx.z;
    const float* W; __nv_bfloat16* Wt; int N;
    if      (sel == 0) { W = w0; Wt = g_wq_v; N = 960; }
    else if (sel == 1) { W = w1; Wt = g_wk_v; N = 320; }
    else if (sel == 2) { W = w2; Wt = g_wv_v; N = 320; }
    else if (sel == 3) { W = w3; Wt = g_wo_v; N = 960; }
    else if (sel == 4) { W = w4; Wt = g_wq_e; N = 960; }
    else if (sel == 5) { W = w5; Wt = g_wk_e; N = 320; }
    else if (sel == 6) { W = w6; Wt = g_wv_e; N = 320; }
    else               { W = w7; Wt = g_wo_e; N = 960; }
    int n0 = blockIdx.x * 32, k0 = blockIdx.y * 32;
    if (n0 >= N) return;
    __shared__ float t[32][33];
    int x = threadIdx.x & 31, y = threadIdx.x >> 5;
    #pragma unroll
    for (int i = 0; i < 32; i += 8)
        t[y+i][x] = W[(size_t)(k0+y+i)*N + n0 + x];
    __syncthreads();
    #pragma unroll
    for (int i = 0; i < 32; i += 8)
        Wt[(size_t)(n0+y+i)*960 + k0 + x] = __float2bfloat16(t[x][y+i]);
}

// ---------------------------------------------------------------------------
// RMSNorm (vectorized): one block per row -> g_xn (bf16)
// ---------------------------------------------------------------------------
__global__ void __launch_bounds__(256) rmsnorm_kernel(
    const float* __restrict__ hv, const float* __restrict__ he,
    const float* __restrict__ lnv, const float* __restrict__ lne)
{
    int r = blockIdx.x;
    int b = r / LT, l = r % LT;
    const float* src; const float* w;
    if (l < LV) { src = hv + ((size_t)b*LV + l)*D_; w = lnv; }
    else        { src = he + ((size_t)b*LE + (l-LV))*D_; w = lne; }
    int tid = threadIdx.x;
    float4 x = make_float4(0.f,0.f,0.f,0.f);
    if (tid < 240) x = ((const float4*)src)[tid];
    float ss = x.x*x.x + x.y*x.y + x.z*x.z + x.w*x.w;
    #pragma unroll
    for (int o = 16; o > 0; o >>= 1) ss += __shfl_xor_sync(0xffffffffu, ss, o);
    __shared__ float red[8];
    if ((tid & 31) == 0) red[tid >> 5] = ss;
    __syncthreads();
    float tot = 0.f;
    #pragma unroll
    for (int i = 0; i < 8; i++) tot += red[i];
    float inv = rsqrtf(tot * (1.0f/D_) + 1e-6f);
    if (tid < 240) {
        float4 wv = ((const float4*)w)[tid];
        uint2 o;
        o.x = pack2(x.x*inv*wv.x, x.y*inv*wv.y);
        o.y = pack2(x.z*inv*wv.z, x.w*inv*wv.w);
        ((uint2*)(g_xn + (size_t)r * D_))[tid] = o;
    }
}

// ---------------------------------------------------------------------------
// Fused bf16 GEMM, 3-stage cp.async ring, ONE syncthreads per k-iter.
// MODE 0: QKV. grid (25, 17, 4). n-tile: [0,15)=Q, [15,20)=K, [20,25)=V.
//         m-tile 16 = expert stream (row0=2048, *_e weights), else VLM.
// MODE 1: O-proj. grid (15, 17, 4). fp32 out + residual (hv / he).
// Tile M=128, N=64, Ktile=32, 30 k-tiles. 8 warps (4m x 2n), 32x32/warp.
// ---------------------------------------------------------------------------
#define TS 40
#define NKT_GEMM 30

template<int MODE>
__global__ void __launch_bounds__(256) fgemm(
    float* __restrict__ Out, const float* __restrict__ Rv, const float* __restrict__ Re)
{
    __shared__ __align__(16) __nv_bfloat16 As[3][128*TS];
    __shared__ __align__(16) __nv_bfloat16 Ws[3][64*TS];

    int nx = blockIdx.x;
    int my = blockIdx.y;
    int b  = blockIdx.z;
    bool is_exp = (my == 16);
    int row0   = is_exp ? 2048 : 0;
    int mb     = is_exp ? 0    : my*128;
    int mvalid = is_exp ? 64   : 2048;

    const __nv_bfloat16* A;
    const __nv_bfloat16* Wt;
    __nv_bfloat16* Cb = nullptr;
    const float* R = nullptr;
    int N, n0, Rrows = 0;
    if (MODE == 0) {
        A = g_xn;
        if (nx < 15)      { Wt = is_exp ? g_wq_e : g_wq_v; Cb = g_q; N = 960; n0 = nx*64; }
        else if (nx < 20) { Wt = is_exp ? g_wk_e : g_wk_v; Cb = g_k; N = 320; n0 = (nx-15)*64; }
        else              { Wt = is_exp ? g_wv_e : g_wv_v; Cb = g_v; N = 320; n0 = (nx-20)*64; }
    } else {
        A = g_at;
        Wt = is_exp ? g_wo_e : g_wo_v;
        R  = is_exp ? Re : Rv;
        Rrows = is_exp ? 64 : 2048;
        N = 960; n0 = nx*64;
    }

    int tid  = threadIdx.x;
    int wid  = tid >> 5, lane = tid & 31;
    int g = lane >> 2, t = lane & 3;
    int wm = wid >> 1, wn = wid & 1;
    int lr = lane & 7, lb1 = (lane >> 3) & 1, lb2 = lane >> 4;

    // per-thread load coords (hoisted)
    int am0 = tid >> 2,        aseg0 = (tid & 3);
    int am1 = (tid+256) >> 2,  aseg1 = ((tid+256) & 3);
    int rl0 = mb + am0; if (rl0 >= mvalid) rl0 = mvalid - 1;
    int rl1 = mb + am1; if (rl1 >= mvalid) rl1 = mvalid - 1;
    const __nv_bfloat16* a_src0 = A + ((size_t)(b*LT + row0 + rl0))*D_ + aseg0*8;
    const __nv_bfloat16* a_src1 = A + ((size_t)(b*LT + row0 + rl1))*D_ + aseg1*8;
    int wn_ = tid >> 2, wseg = tid & 3;
    const __nv_bfloat16* w_src = Wt + (size_t)(n0 + wn_)*960 + wseg*8;

    float acc[2][4][4] = {};

    // prologue: prefetch stages 0 and 1
    {
        cp16(&As[0][am0*TS + aseg0*8], a_src0);
        cp16(&As[0][am1*TS + aseg1*8], a_src1);
        cp16(&Ws[0][wn_*TS + wseg*8], w_src);
        cp_commit();
        cp16(&As[1][am0*TS + aseg0*8], a_src0 + 32);
        cp16(&As[1][am1*TS + aseg1*8], a_src1 + 32);
        cp16(&Ws[1][wn_*TS + wseg*8], w_src + 32);
        cp_commit();
    }

    int s = 0;       // stage of iteration it
    int ps = 2;      // stage to prefetch (it+2)
    for (int it = 0; it < NKT_GEMM; it++) {
        if (it < NKT_GEMM - 2) cp_wait1(); else cp_wait0();
        __syncthreads();
        if (it + 2 < NKT_GEMM) {
            int k0 = (it+2)*32;
            cp16(&As[ps][am0*TS + aseg0*8], a_src0 + k0);
            cp16(&As[ps][am1*TS + aseg1*8], a_src1 + k0);
            cp16(&Ws[ps][wn_*TS + wseg*8], w_src + k0);
            cp_commit();
        }

        #pragma unroll
        for (int ks = 0; ks < 2; ks++) {
            int kb = ks*16;
            uint32_t a[2][4];
            #pragma unroll
            for (int mt = 0; mt < 2; mt++)
                ldsm4(a[mt], &As[s][(wm*32 + mt*16 + lr + lb1*8)*TS + kb + lb2*8]);
            #pragma unroll
            for (int ntp = 0; ntp < 2; ntp++) {
                uint32_t bq[4];
                ldsm4(bq, &Ws[s][(wn*32 + ntp*16 + lr + lb2*8)*TS + kb + lb1*8]);
                #pragma unroll
                for (int mt = 0; mt < 2; mt++) {
                    mma16(acc[mt][2*ntp  ], a[mt], bq[0], bq[1]);
                    mma16(acc[mt][2*ntp+1], a[mt], bq[2], bq[3]);
                }
            }
        }
        s  = (s  == 2) ? 0 : s + 1;
        ps = (ps == 2) ? 0 : ps + 1;
    }

    #pragma unroll
    for (int mt = 0; mt < 2; mt++) {
        #pragma unroll
        for (int nt = 0; nt < 4; nt++) {
            int col = n0 + wn*32 + nt*8 + 2*t;
            int m0r = mb + wm*32 + mt*16 + g;
            int m1r = m0r + 8;
            if (MODE == 1) {
                if (m0r < mvalid) {
                    float2 rv = *(const float2*)(R + ((size_t)b*Rrows + m0r)*D_ + col);
                    float2 o = make_float2(acc[mt][nt][0] + rv.x, acc[mt][nt][1] + rv.y);
                    *(float2*)(Out + ((size_t)(b*LT + row0 + m0r))*D_ + col) = o;
                }
                if (m1r < mvalid) {
                    float2 rv = *(const float2*)(R + ((size_t)b*Rrows + m1r)*D_ + col);
                    float2 o = make_float2(acc[mt][nt][2] + rv.x, acc[mt][nt][3] + rv.y);
                    *(float2*)(Out + ((size_t)(b*LT + row0 + m1r))*D_ + col) = o;
                }
            } else {
                if (m0r < mvalid)
                    *(uint32_t*)&Cb[((size_t)(b*LT + row0 + m0r))*N + col] =
                        pack2(acc[mt][nt][0], acc[mt][nt][1]);
                if (m1r < mvalid)
                    *(uint32_t*)&Cb[((size_t)(b*LT + row0 + m1r))*N + col] =
                        pack2(acc[mt][nt][2], acc[mt][nt][3]);
            }
        }
    }
}

// ---------------------------------------------------------------------------
// RoPE in-place (cheap transcendentals): exp2f timescale + Cody-Waite mod 2pi
// + __sincosf. g_q folds 0.125 scale. One warp per (row, head).
// ---------------------------------------------------------------------------
__global__ void __launch_bounds__(256) rope_kernel(
    const int* __restrict__ pos_v, const int* __restrict__ pos_e)
{
    int w    = blockIdx.x * 8 + (threadIdx.x >> 5);
    int lane = threadIdx.x & 31;
    int row = w / 20;
    int hh  = w % 20;
    int b = row / LT, l = row % LT;
    int p = (l < LV) ? pos_v[b*LV + l] : pos_e[b*LE + (l - LV)];
    // invts = 10000^(-lane/32) = 2^(-lane*log2(10000)/32)
    float invts = exp2f((float)lane * -0.41524101186407974f);
    float rad = (float)p * invts;
    // range-reduce mod 2*pi (Cody-Waite; C1 exact in 9 bits, k <= 336)
    float kk = rintf(rad * 0.15915494309189535f);
    float r  = fmaf(-kk, 6.28125f, rad);
    r = fmaf(-kk, 0.0019353071795864769f, r);
    float sn, cs;
    __sincosf(r, &sn, &cs);
    bool isq = (hh < H_);
    __nv_bfloat16* base = isq ? (g_q + (size_t)row*D_  + hh*HD_)
                              : (g_k + (size_t)row*NKV + (hh - H_)*HD_);
    float x1 = __bfloat162float(base[lane]);
    float x2 = __bfloat162float(base[lane + 32]);
    float sc = isq ? 0.125f : 1.0f;
    base[lane]      = __float2bfloat16((x1*cs - x2*sn) * sc);
    base[lane + 32] = __float2bfloat16((x2*cs + x1*sn) * sc);
}

// ---------------------------------------------------------------------------
// bf16 flash attention (m16n8k16 + ldmatrix + cp.async double buffering).
// PROVEN round-9 pipeline structure (2 syncthreads per kv-iter).
// Tile 128q x 64k, 8 warps x 16 q rows. K,V natural [key][d], stride 72 halfs.
// Grid (17, 15, 4); qt 16 = expert rows (causal over expert keys).
// ---------------------------------------------------------------------------
#define KS 72

__global__ void __launch_bounds__(256) attn_tc()
{
    __shared__ __align__(16) __nv_bfloat16 Ksm[2][64*KS];
    __shared__ __align__(16) __nv_bfloat16 Vsm[2][64*KS];

    int qt = blockIdx.x, h = blockIdx.y, b = blockIdx.z;
    int kvh = h / 3;
    int tid = threadIdx.x;
    int w = tid >> 5, lane = tid & 31;
    int g = lane >> 2, t = lane & 3;
    int lr = lane & 7, lb1 = (lane >> 3) & 1, lb2 = lane >> 4;
    int q0  = qt * 128;
    int qr0 = w * 16;
    bool is_exp = (qt == 16);
    int nkt = is_exp ? 33 : 32;

    // per-thread KV load coords (hoisted): 2 chunks per array
    int key0 = tid >> 3,        seg0 = (tid & 7);
    int key1 = (tid+256) >> 3,  seg1 = ((tid+256) & 7);
    const __nv_bfloat16* k_src0 = g_k + ((size_t)(b*LT + key0))*NKV + kvh*HD_ + seg0*8;
    const __nv_bfloat16* k_src1 = g_k + ((size_t)(b*LT + key1))*NKV + kvh*HD_ + seg1*8;
    const __nv_bfloat16* v_src0 = g_v + ((size_t)(b*LT + key0))*NKV + kvh*HD_ + seg0*8;
    const __nv_bfloat16* v_src1 = g_v + ((size_t)(b*LT + key1))*NKV + kvh*HD_ + seg1*8;

    // Q fragments (pre-scaled by rope): 4 k16-steps x 4 pair regs
    uint32_t qa[4][4];
    {
        int r0 = q0 + qr0 + g;     if (r0 > LT-1) r0 = LT-1;
        int r1 = q0 + qr0 + g + 8; if (r1 > LT-1) r1 = LT-1;
        const __nv_bfloat16* p0 = g_q + ((size_t)(b*LT + r0))*D_ + h*HD_;
        const __nv_bfloat16* p1 = g_q + ((size_t)(b*LT + r1))*D_ + h*HD_;
        #pragma unroll
        for (int ks = 0; ks < 4; ks++) {
            int kb = ks*16;
            qa[ks][0] = *(const uint32_t*)(p0 + kb + 2*t);
            qa[ks][1] = *(const uint32_t*)(p1 + kb + 2*t);
            qa[ks][2] = *(const uint32_t*)(p0 + kb + 2*t + 8);
            qa[ks][3] = *(const uint32_t*)(p1 + kb + 2*t + 8);
        }
    }

    float o[8][4] = {};
    float m2[2] = {-1e30f, -1e30f};
    float l2[2] = {0.f, 0.f};

    // prologue: prefetch kv-tile 0
    {
        cp16(&Ksm[0][key0*KS + seg0*8], k_src0);
        cp16(&Ksm[0][key1*KS + seg1*8], k_src1);
        cp16(&Vsm[0][key0*KS + seg0*8], v_src0);
        cp16(&Vsm[0][key1*KS + seg1*8], v_src1);
        cp_commit();
    }

    for (int kt = 0; kt < nkt; kt++) {
        int buf = kt & 1;
        if (kt + 1 < nkt) {
            size_t off = (size_t)(kt+1)*64*NKV;
            cp16(&Ksm[buf^1][key0*KS + seg0*8], k_src0 + off);
            cp16(&Ksm[buf^1][key1*KS + seg1*8], k_src1 + off);
            cp16(&Vsm[buf^1][key0*KS + seg0*8], v_src0 + off);
            cp16(&Vsm[buf^1][key1*KS + seg1*8], v_src1 + off);
            cp_commit();
            cp_wait1();
        } else {
            cp_wait0();
        }
        __syncthreads();

        // S = Q K^T (16q x 64k per warp)
        float sacc[8][4] = {};
        #pragma unroll
        for (int ks = 0; ks < 4; ks++) {
            int kb = ks*16;
            #pragma unroll
            for (int ntp = 0; ntp < 4; ntp++) {
                uint32_t bq[4];
                ldsm4(bq, &Ksm[buf][(ntp*16 + lr + lb2*8)*KS + kb + lb1*8]);
                mma16(sacc[2*ntp  ], qa[ks], bq[0], bq[1]);
                mma16(sacc[2*ntp+1], qa[ks], bq[2], bq[3]);
            }
        }
        // causal mask in expert/expert block
        if (is_exp && kt == 32) {
            int qe0 = qr0 + g, qe1 = qe0 + 8;
            #pragma unroll
            for (int nt = 0; nt < 8; nt++) {
                int c0 = nt*8 + 2*t, c1 = c0 + 1;
                if (c0 > qe0) sacc[nt][0] = -1e30f;
                if (c1 > qe0) sacc[nt][1] = -1e30f;
                if (c0 > qe1) sacc[nt][2] = -1e30f;
                if (c1 > qe1) sacc[nt][3] = -1e30f;
            }
        }
        // online softmax per row-half (rows g and g+8)
        #pragma unroll
        for (int hh = 0; hh < 2; hh++) {
            float rm = -1e30f;
            #pragma unroll
            for (int nt = 0; nt < 8; nt++)
                rm = fmaxf(rm, fmaxf(sacc[nt][hh*2], sacc[nt][hh*2+1]));
            rm = fmaxf(rm, __shfl_xor_sync(0xffffffffu, rm, 1));
            rm = fmaxf(rm, __shfl_xor_sync(0xffffffffu, rm, 2));
            float mn = fmaxf(m2[hh], rm);
            float alpha = __expf(m2[hh] - mn);
            float sum = 0.f;
            #pragma unroll
            for (int nt = 0; nt < 8; nt++) {
                float p0 = __expf(sacc[nt][hh*2  ] - mn);
                float p1 = __expf(sacc[nt][hh*2+1] - mn);
                sacc[nt][hh*2] = p0; sacc[nt][hh*2+1] = p1;
                sum += p0 + p1;
            }
            sum += __shfl_xor_sync(0xffffffffu, sum, 1);
            sum += __shfl_xor_sync(0xffffffffu, sum, 2);
            l2[hh] = l2[hh]*alpha + sum;
            m2[hh] = mn;
            #pragma unroll
            for (int nt = 0; nt < 8; nt++) {
                o[nt][hh*2]   *= alpha;
                o[nt][hh*2+1] *= alpha;
            }
        }
        // O += P V (P A-frag packed straight from S C-frag; V via LDSM.trans)
        #pragma unroll
        for (int ks = 0; ks < 4; ks++) {
            int kb = ks*16;
            uint32_t pa[4];
            pa[0] = pack2(sacc[2*ks  ][0], sacc[2*ks  ][1]);
            pa[1] = pack2(sacc[2*ks  ][2], sacc[2*ks  ][3]);
            pa[2] = pack2(sacc[2*ks+1][0], sacc[2*ks+1][1]);
            pa[3] = pack2(sacc[2*ks+1][2], sacc[2*ks+1][3]);
            #pragma unroll
            for (int ntp = 0; ntp < 4; ntp++) {
                uint32_t bq[4];
                ldsm4t(bq, &Vsm[buf][(kb + lr + lb1*8)*KS + ntp*16 + lb2*8]);
                mma16(o[2*ntp  ], pa, bq[0], bq[1]);
                mma16(o[2*ntp+1], pa, bq[2], bq[3]);
            }
        }
        __syncthreads();
    }

    // normalize + store bf16
    float inv0 = 1.0f / l2[0];
    float inv1 = 1.0f / l2[1];
    int r0 = q0 + qr0 + g;
    int r1 = r0 + 8;
    #pragma unroll
    for (int nt = 0; nt < 8; nt++) {
        int col = h*HD_ + nt*8 + 2*t;
        if (r0 < LT)
            *(uint32_t*)&g_at[((size_t)(b*LT + r0))*D_ + col] =
                pack2(o[nt][0]*inv0, o[nt][1]*inv0);
        if (r1 < LT)
            *(uint32_t*)&g_at[((size_t)(b*LT + r1))*D_ + col] =
                pack2(o[nt][2]*inv1, o[nt][3]*inv1);
    }
}

// ---------------------------------------------------------------------------
// kernel_launch: ONLY kernel launches (graph-capture friendly).
// ---------------------------------------------------------------------------
extern "C" void kernel_launch(void* const* d_in, const int* in_sizes, int n_in,
                              void* d_out, int out_size)
{
    const float* hv   = (const float*)d_in[0];
    const float* he   = (const float*)d_in[1];
    const float* lnv  = (const float*)d_in[2];
    const float* wq_v = (const float*)d_in[3];
    const float* wk_v = (const float*)d_in[4];
    const float* wv_v = (const float*)d_in[5];
    const float* wo_v = (const float*)d_in[6];
    const float* lne  = (const float*)d_in[7];
    const float* wq_e = (const float*)d_in[8];
    const float* wk_e = (const float*)d_in[9];
    const float* wv_e = (const float*)d_in[10];
    const float* wo_e = (const float*)d_in[11];
    const int*   posv = (const int*)d_in[12];
    const int*   pose = (const int*)d_in[13];
    float* out = (float*)d_out;

    // fused weight convert+transpose to bf16 [n][k]
    wconv_all<<<dim3(30,30,8), 256>>>(wq_v, wk_v, wv_v, wo_v, wq_e, wk_e, wv_e, wo_e);

    rmsnorm_kernel<<<B_*LT, 256>>>(hv, he, lnv, lne);

    // fused QKV projection, both streams
    fgemm<0><<<dim3(25,17,4), 256>>>(nullptr, nullptr, nullptr);

    rope_kernel<<<(B_*LT*20)/8, 256>>>(posv, pose);

    attn_tc<<<dim3(17,15,4), 256>>>();

    // fused output projection + residual, both streams
    fgemm<1><<<dim3(15,17,4), 256>>>(out, hv, he);
}

// round 14
// speedup vs baseline: 8.8749x; 1.0434x over previous
#include <cuda_runtime.h>
#include <cuda_bf16.h>
#include <math.h>
#include <stdint.h>

// Problem constants
#define B_   4
#define LV   2048
#define LE   64
#define LT   2112      // LV + LE
#define D_   960
#define H_   15
#define KVH_ 5
#define HD_  64
#define NKV  320       // KVH_*HD_

// Scratch (device globals; bf16 activations)
__device__ __nv_bfloat16 g_xn[B_*LT*D_];
__device__ __nv_bfloat16 g_q [B_*LT*D_];
__device__ __nv_bfloat16 g_k [B_*LT*NKV];
__device__ __nv_bfloat16 g_v [B_*LT*NKV];
__device__ __nv_bfloat16 g_at[B_*LT*D_];
// bf16 transposed weights [n][k], k stride 960
__device__ __nv_bfloat16 g_wq_v[960*960];
__device__ __nv_bfloat16 g_wk_v[320*960];
__device__ __nv_bfloat16 g_wv_v[320*960];
__device__ __nv_bfloat16 g_wo_v[960*960];
__device__ __nv_bfloat16 g_wq_e[960*960];
__device__ __nv_bfloat16 g_wk_e[320*960];
__device__ __nv_bfloat16 g_wv_e[320*960];
__device__ __nv_bfloat16 g_wo_e[960*960];

// ---------------------------------------------------------------------------
// helpers
// ---------------------------------------------------------------------------
__device__ __forceinline__ uint32_t pack2(float lo, float hi) {
    __nv_bfloat162 h = __floats2bfloat162_rn(lo, hi);
    return *(uint32_t*)&h;
}
__device__ __forceinline__ void mma16(float* c, const uint32_t* a, uint32_t b0, uint32_t b1) {
    asm("mma.sync.aligned.m16n8k16.row.col.f32.bf16.bf16.f32 "
        "{%0,%1,%2,%3}, {%4,%5,%6,%7}, {%8,%9}, {%0,%1,%2,%3};"
        : "+f"(c[0]), "+f"(c[1]), "+f"(c[2]), "+f"(c[3])
        : "r"(a[0]), "r"(a[1]), "r"(a[2]), "r"(a[3]), "r"(b0), "r"(b1));
}
__device__ __forceinline__ void ldsm4(uint32_t* r, const __nv_bfloat16* p) {
    uint32_t a = (uint32_t)__cvta_generic_to_shared(p);
    asm volatile("ldmatrix.sync.aligned.m8n8.x4.shared.b16 {%0,%1,%2,%3}, [%4];"
        : "=r"(r[0]), "=r"(r[1]), "=r"(r[2]), "=r"(r[3]) : "r"(a));
}
__device__ __forceinline__ void ldsm4t(uint32_t* r, const __nv_bfloat16* p) {
    uint32_t a = (uint32_t)__cvta_generic_to_shared(p);
    asm volatile("ldmatrix.sync.aligned.m8n8.x4.trans.shared.b16 {%0,%1,%2,%3}, [%4];"
        : "=r"(r[0]), "=r"(r[1]), "=r"(r[2]), "=r"(r[3]) : "r"(a));
}
__device__ __forceinline__ void cp16(__nv_bfloat16* smem, const __nv_bfloat16* gmem) {
    uint32_t a = (uint32_t)__cvta_generic_to_shared(smem);
    asm volatile("cp.async.cg.shared.global [%0], [%1], 16;" :: "r"(a), "l"(gmem));
}
__device__ __forceinline__ void cp_commit() { asm volatile("cp.async.commit_group;"); }
__device__ __forceinline__ void cp_wait1()  { asm volatile("cp.async.wait_group 1;"); }
__device__ __forceinline__ void cp_wait0()  { asm volatile("cp.async.wait_group 0;"); }

// ---------------------------------------------------------------------------
// Fused weight convert + transpose for all 8 weights.
// W[k][n] fp32 -> Wt[n][k] bf16 (k stride 960). Block = 256. Grid (30,30,8).
// ---------------------------------------------------------------------------
__global__ void __launch_bounds__(256) wconv_all(
    const float* w0, const float* w1, const float* w2, const float* w3,
    const float* w4, const float* w5, const float* w6, const float* w7)
{
    int sel = blockIdx.z;
    const float* W; __nv_bfloat16* Wt; int N;
    if      (sel == 0) { W = w0; Wt = g_wq_v; N = 960; }
    else if (sel == 1) { W = w1; Wt = g_wk_v; N = 320; }
    else if (sel == 2) { W = w2; Wt = g_wv_v; N = 320; }
    else if (sel == 3) { W = w3; Wt = g_wo_v; N = 960; }
    else if (sel == 4) { W = w4; Wt = g_wq_e; N = 960; }
    else if (sel == 5) { W = w5; Wt = g_wk_e; N = 320; }
    else if (sel == 6) { W = w6; Wt = g_wv_e; N = 320; }
    else               { W = w7; Wt = g_wo_e; N = 960; }
    int n0 = blockIdx.x * 32, k0 = blockIdx.y * 32;
    if (n0 >= N) return;
    __shared__ float t[32][33];
    int x = threadIdx.x & 31, y = threadIdx.x >> 5;
    #pragma unroll
    for (int i = 0; i < 32; i += 8)
        t[y+i][x] = W[(size_t)(k0+y+i)*N + n0 + x];
    __syncthreads();
    #pragma unroll
    for (int i = 0; i < 32; i += 8)
        Wt[(size_t)(n0+y+i)*960 + k0 + x] = __float2bfloat16(t[x][y+i]);
}

// ---------------------------------------------------------------------------
// RMSNorm (vectorized): one block per row -> g_xn (bf16)
// ---------------------------------------------------------------------------
__global__ void __launch_bounds__(256) rmsnorm_kernel(
    const float* __restrict__ hv, const float* __restrict__ he,
    const float* __restrict__ lnv, const float* __restrict__ lne)
{
    int r = blockIdx.x;
    int b = r / LT, l = r % LT;
    const float* src; const float* w;
    if (l < LV) { src = hv + ((size_t)b*LV + l)*D_; w = lnv; }
    else        { src = he + ((size_t)b*LE + (l-LV))*D_; w = lne; }
    int tid = threadIdx.x;
    float4 x = make_float4(0.f,0.f,0.f,0.f);
    if (tid < 240) x = ((const float4*)src)[tid];
    float ss = x.x*x.x + x.y*x.y + x.z*x.z + x.w*x.w;
    #pragma unroll
    for (int o = 16; o > 0; o >>= 1) ss += __shfl_xor_sync(0xffffffffu, ss, o);
    __shared__ float red[8];
    if ((tid & 31) == 0) red[tid >> 5] = ss;
    __syncthreads();
    float tot = 0.f;
    #pragma unroll
    for (int i = 0; i < 8; i++) tot += red[i];
    float inv = rsqrtf(tot * (1.0f/D_) + 1e-6f);
    if (tid < 240) {
        float4 wv = ((const float4*)w)[tid];
        uint2 o;
        o.x = pack2(x.x*inv*wv.x, x.y*inv*wv.y);
        o.y = pack2(x.z*inv*wv.z, x.w*inv*wv.w);
        ((uint2*)(g_xn + (size_t)r * D_))[tid] = o;
    }
}

// ---------------------------------------------------------------------------
// Fused bf16 GEMM, 3-stage cp.async ring, ONE syncthreads per k-iter.
// MODE 0: QKV. grid (25, 17, 4). MODE 1: O-proj. grid (15, 17, 4).
// Tile M=128, N=64, Ktile=32, 30 k-tiles. 8 warps (4m x 2n), 32x32/warp.
// ---------------------------------------------------------------------------
#define TS 40
#define NKT_GEMM 30

template<int MODE>
__global__ void __launch_bounds__(256) fgemm(
    float* __restrict__ Out, const float* __restrict__ Rv, const float* __restrict__ Re)
{
    __shared__ __align__(16) __nv_bfloat16 As[3][128*TS];
    __shared__ __align__(16) __nv_bfloat16 Ws[3][64*TS];

    int nx = blockIdx.x;
    int my = blockIdx.y;
    int b  = blockIdx.z;
    bool is_exp = (my == 16);
    int row0   = is_exp ? 2048 : 0;
    int mb     = is_exp ? 0    : my*128;
    int mvalid = is_exp ? 64   : 2048;

    const __nv_bfloat16* A;
    const __nv_bfloat16* Wt;
    __nv_bfloat16* Cb = nullptr;
    const float* R = nullptr;
    int N, n0, Rrows = 0;
    if (MODE == 0) {
        A = g_xn;
        if (nx < 15)      { Wt = is_exp ? g_wq_e : g_wq_v; Cb = g_q; N = 960; n0 = nx*64; }
        else if (nx < 20) { Wt = is_exp ? g_wk_e : g_wk_v; Cb = g_k; N = 320; n0 = (nx-15)*64; }
        else              { Wt = is_exp ? g_wv_e : g_wv_v; Cb = g_v; N = 320; n0 = (nx-20)*64; }
    } else {
        A = g_at;
        Wt = is_exp ? g_wo_e : g_wo_v;
        R  = is_exp ? Re : Rv;
        Rrows = is_exp ? 64 : 2048;
        N = 960; n0 = nx*64;
    }

    int tid  = threadIdx.x;
    int wid  = tid >> 5, lane = tid & 31;
    int g = lane >> 2, t = lane & 3;
    int wm = wid >> 1, wn = wid & 1;
    int lr = lane & 7, lb1 = (lane >> 3) & 1, lb2 = lane >> 4;

    // per-thread load coords (hoisted)
    int am0 = tid >> 2,        aseg0 = (tid & 3);
    int am1 = (tid+256) >> 2,  aseg1 = ((tid+256) & 3);
    int rl0 = mb + am0; if (rl0 >= mvalid) rl0 = mvalid - 1;
    int rl1 = mb + am1; if (rl1 >= mvalid) rl1 = mvalid - 1;
    const __nv_bfloat16* a_src0 = A + ((size_t)(b*LT + row0 + rl0))*D_ + aseg0*8;
    const __nv_bfloat16* a_src1 = A + ((size_t)(b*LT + row0 + rl1))*D_ + aseg1*8;
    int wn_ = tid >> 2, wseg = tid & 3;
    const __nv_bfloat16* w_src = Wt + (size_t)(n0 + wn_)*960 + wseg*8;

    float acc[2][4][4] = {};

    // prologue: prefetch stages 0 and 1
    {
        cp16(&As[0][am0*TS + aseg0*8], a_src0);
        cp16(&As[0][am1*TS + aseg1*8], a_src1);
        cp16(&Ws[0][wn_*TS + wseg*8], w_src);
        cp_commit();
        cp16(&As[1][am0*TS + aseg0*8], a_src0 + 32);
        cp16(&As[1][am1*TS + aseg1*8], a_src1 + 32);
        cp16(&Ws[1][wn_*TS + wseg*8], w_src + 32);
        cp_commit();
    }

    int s = 0;       // stage of iteration it
    int ps = 2;      // stage to prefetch (it+2)
    for (int it = 0; it < NKT_GEMM; it++) {
        if (it < NKT_GEMM - 2) cp_wait1(); else cp_wait0();
        __syncthreads();
        if (it + 2 < NKT_GEMM) {
            int k0 = (it+2)*32;
            cp16(&As[ps][am0*TS + aseg0*8], a_src0 + k0);
            cp16(&As[ps][am1*TS + aseg1*8], a_src1 + k0);
            cp16(&Ws[ps][wn_*TS + wseg*8], w_src + k0);
            cp_commit();
        }

        #pragma unroll
        for (int ks = 0; ks < 2; ks++) {
            int kb = ks*16;
            uint32_t a[2][4];
            #pragma unroll
            for (int mt = 0; mt < 2; mt++)
                ldsm4(a[mt], &As[s][(wm*32 + mt*16 + lr + lb1*8)*TS + kb + lb2*8]);
            #pragma unroll
            for (int ntp = 0; ntp < 2; ntp++) {
                uint32_t bq[4];
                ldsm4(bq, &Ws[s][(wn*32 + ntp*16 + lr + lb2*8)*TS + kb + lb1*8]);
                #pragma unroll
                for (int mt = 0; mt < 2; mt++) {
                    mma16(acc[mt][2*ntp  ], a[mt], bq[0], bq[1]);
                    mma16(acc[mt][2*ntp+1], a[mt], bq[2], bq[3]);
                }
            }
        }
        s  = (s  == 2) ? 0 : s + 1;
        ps = (ps == 2) ? 0 : ps + 1;
    }

    #pragma unroll
    for (int mt = 0; mt < 2; mt++) {
        #pragma unroll
        for (int nt = 0; nt < 4; nt++) {
            int col = n0 + wn*32 + nt*8 + 2*t;
            int m0r = mb + wm*32 + mt*16 + g;
            int m1r = m0r + 8;
            if (MODE == 1) {
                if (m0r < mvalid) {
                    float2 rv = *(const float2*)(R + ((size_t)b*Rrows + m0r)*D_ + col);
                    float2 o = make_float2(acc[mt][nt][0] + rv.x, acc[mt][nt][1] + rv.y);
                    *(float2*)(Out + ((size_t)(b*LT + row0 + m0r))*D_ + col) = o;
                }
                if (m1r < mvalid) {
                    float2 rv = *(const float2*)(R + ((size_t)b*Rrows + m1r)*D_ + col);
                    float2 o = make_float2(acc[mt][nt][2] + rv.x, acc[mt][nt][3] + rv.y);
                    *(float2*)(Out + ((size_t)(b*LT + row0 + m1r))*D_ + col) = o;
                }
            } else {
                if (m0r < mvalid)
                    *(uint32_t*)&Cb[((size_t)(b*LT + row0 + m0r))*N + col] =
                        pack2(acc[mt][nt][0], acc[mt][nt][1]);
                if (m1r < mvalid)
                    *(uint32_t*)&Cb[((size_t)(b*LT + row0 + m1r))*N + col] =
                        pack2(acc[mt][nt][2], acc[mt][nt][3]);
            }
        }
    }
}

// ---------------------------------------------------------------------------
// RoPE v2: ONE warp per row, sincos computed ONCE, looped over all 20 heads.
// Q gets scale 0.125*log2(e) (softmax runs in log2 space); K gets 1.0.
// Grid: B_*LT/8 blocks x 256 threads (8 warps).
// ---------------------------------------------------------------------------
__global__ void __launch_bounds__(256) rope_kernel(
    const int* __restrict__ pos_v, const int* __restrict__ pos_e)
{
    int row  = blockIdx.x * 8 + (threadIdx.x >> 5);
    int lane = threadIdx.x & 31;
    int b = row / LT, l = row % LT;
    int p = (l < LV) ? pos_v[b*LV + l] : pos_e[b*LE + (l - LV)];
    // invts = 10000^(-lane/32) = 2^(-lane*log2(10000)/32)
    float invts = exp2f((float)lane * -0.41524101186407974f);
    float rad = (float)p * invts;
    // range-reduce mod 2*pi (Cody-Waite; C1 exact in 9 bits, k <= 336)
    float kk = rintf(rad * 0.15915494309189535f);
    float r  = fmaf(-kk, 6.28125f, rad);
    r = fmaf(-kk, 0.0019353071795864769f, r);
    float sn, cs;
    __sincosf(r, &sn, &cs);

    const float QSC = 0.125f * 1.4426950408889634f;  // fold log2e for exp2 softmax
    __nv_bfloat16* qbase = g_q + (size_t)row*D_;
    #pragma unroll
    for (int hh = 0; hh < H_; hh++) {
        __nv_bfloat16* base = qbase + hh*HD_;
        float x1 = __bfloat162float(base[lane]);
        float x2 = __bfloat162float(base[lane + 32]);
        base[lane]      = __float2bfloat16((x1*cs - x2*sn) * QSC);
        base[lane + 32] = __float2bfloat16((x2*cs + x1*sn) * QSC);
    }
    __nv_bfloat16* kbase = g_k + (size_t)row*NKV;
    #pragma unroll
    for (int hh = 0; hh < KVH_; hh++) {
        __nv_bfloat16* base = kbase + hh*HD_;
        float x1 = __bfloat162float(base[lane]);
        float x2 = __bfloat162float(base[lane + 32]);
        base[lane]      = __float2bfloat16(x1*cs - x2*sn);
        base[lane + 32] = __float2bfloat16(x2*cs + x1*sn);
    }
}

// ---------------------------------------------------------------------------
// bf16 flash attention (m16n8k16 + ldmatrix + cp.async double buffering).
// PROVEN 2-sync pipeline. Softmax in log2 space (Q pre-scaled by log2e).
// Tile 128q x 64k, 8 warps x 16 q rows. K,V natural [key][d], stride 72 halfs.
// Grid (17, 15, 4); qt 16 = expert rows (causal over expert keys).
// ---------------------------------------------------------------------------
#define KS 72

__global__ void __launch_bounds__(256) attn_tc()
{
    __shared__ __align__(16) __nv_bfloat16 Ksm[2][64*KS];
    __shared__ __align__(16) __nv_bfloat16 Vsm[2][64*KS];

    int qt = blockIdx.x, h = blockIdx.y, b = blockIdx.z;
    int kvh = h / 3;
    int tid = threadIdx.x;
    int w = tid >> 5, lane = tid & 31;
    int g = lane >> 2, t = lane & 3;
    int lr = lane & 7, lb1 = (lane >> 3) & 1, lb2 = lane >> 4;
    int q0  = qt * 128;
    int qr0 = w * 16;
    bool is_exp = (qt == 16);
    int nkt = is_exp ? 33 : 32;

    // per-thread KV load coords (hoisted): 2 chunks per array
    int key0 = tid >> 3,        seg0 = (tid & 7);
    int key1 = (tid+256) >> 3,  seg1 = ((tid+256) & 7);
    const __nv_bfloat16* k_src0 = g_k + ((size_t)(b*LT + key0))*NKV + kvh*HD_ + seg0*8;
    const __nv_bfloat16* k_src1 = g_k + ((size_t)(b*LT + key1))*NKV + kvh*HD_ + seg1*8;
    const __nv_bfloat16* v_src0 = g_v + ((size_t)(b*LT + key0))*NKV + kvh*HD_ + seg0*8;
    const __nv_bfloat16* v_src1 = g_v + ((size_t)(b*LT + key1))*NKV + kvh*HD_ + seg1*8;

    // Q fragments (pre-scaled by rope): 4 k16-steps x 4 pair regs
    uint32_t qa[4][4];
    {
        int r0 = q0 + qr0 + g;     if (r0 > LT-1) r0 = LT-1;
        int r1 = q0 + qr0 + g + 8; if (r1 > LT-1) r1 = LT-1;
        const __nv_bfloat16* p0 = g_q + ((size_t)(b*LT + r0))*D_ + h*HD_;
        const __nv_bfloat16* p1 = g_q + ((size_t)(b*LT + r1))*D_ + h*HD_;
        #pragma unroll
        for (int ks = 0; ks < 4; ks++) {
            int kb = ks*16;
            qa[ks][0] = *(const uint32_t*)(p0 + kb + 2*t);
            qa[ks][1] = *(const uint32_t*)(p1 + kb + 2*t);
            qa[ks][2] = *(const uint32_t*)(p0 + kb + 2*t + 8);
            qa[ks][3] = *(const uint32_t*)(p1 + kb + 2*t + 8);
        }
    }

    float o[8][4] = {};
    float m2[2] = {-1e30f, -1e30f};
    float l2[2] = {0.f, 0.f};

    // prologue: prefetch kv-tile 0
    {
        cp16(&Ksm[0][key0*KS + seg0*8], k_src0);
        cp16(&Ksm[0][key1*KS + seg1*8], k_src1);
        cp16(&Vsm[0][key0*KS + seg0*8], v_src0);
        cp16(&Vsm[0][key1*KS + seg1*8], v_src1);
        cp_commit();
    }

    for (int kt = 0; kt < nkt; kt++) {
        int buf = kt & 1;
        if (kt + 1 < nkt) {
            size_t off = (size_t)(kt+1)*64*NKV;
            cp16(&Ksm[buf^1][key0*KS + seg0*8], k_src0 + off);
            cp16(&Ksm[buf^1][key1*KS + seg1*8], k_src1 + off);
            cp16(&Vsm[buf^1][key0*KS + seg0*8], v_src0 + off);
            cp16(&Vsm[buf^1][key1*KS + seg1*8], v_src1 + off);
            cp_commit();
            cp_wait1();
        } else {
            cp_wait0();
        }
        __syncthreads();

        // S = Q K^T (16q x 64k per warp); scores in log2 units
        float sacc[8][4] = {};
        #pragma unroll
        for (int ks = 0; ks < 4; ks++) {
            int kb = ks*16;
            #pragma unroll
            for (int ntp = 0; ntp < 4; ntp++) {
                uint32_t bq[4];
                ldsm4(bq, &Ksm[buf][(ntp*16 + lr + lb2*8)*KS + kb + lb1*8]);
                mma16(sacc[2*ntp  ], qa[ks], bq[0], bq[1]);
                mma16(sacc[2*ntp+1], qa[ks], bq[2], bq[3]);
            }
        }
        // causal mask in expert/expert block
        if (is_exp && kt == 32) {
            int qe0 = qr0 + g, qe1 = qe0 + 8;
            #pragma unroll
            for (int nt = 0; nt < 8; nt++) {
                int c0 = nt*8 + 2*t, c1 = c0 + 1;
                if (c0 > qe0) sacc[nt][0] = -1e30f;
                if (c1 > qe0) sacc[nt][1] = -1e30f;
                if (c0 > qe1) sacc[nt][2] = -1e30f;
                if (c1 > qe1) sacc[nt][3] = -1e30f;
            }
        }
        // online softmax per row-half (rows g and g+8), log2 space: exp2f only
        #pragma unroll
        for (int hh = 0; hh < 2; hh++) {
            float rm = -1e30f;
            #pragma unroll
            for (int nt = 0; nt < 8; nt++)
                rm = fmaxf(rm, fmaxf(sacc[nt][hh*2], sacc[nt][hh*2+1]));
            rm = fmaxf(rm, __shfl_xor_sync(0xffffffffu, rm, 1));
            rm = fmaxf(rm, __shfl_xor_sync(0xffffffffu, rm, 2));
            float mn = fmaxf(m2[hh], rm);
            float alpha = exp2f(m2[hh] - mn);
            float sum = 0.f;
            #pragma unroll
            for (int nt = 0; nt < 8; nt++) {
                float p0 = exp2f(sacc[nt][hh*2  ] - mn);
                float p1 = exp2f(sacc[nt][hh*2+1] - mn);
                sacc[nt][hh*2] = p0; sacc[nt][hh*2+1] = p1;
                sum += p0 + p1;
            }
            sum += __shfl_xor_sync(0xffffffffu, sum, 1);
            sum += __shfl_xor_sync(0xffffffffu, sum, 2);
            l2[hh] = l2[hh]*alpha + sum;
            m2[hh] = mn;
            #pragma unroll
            for (int nt = 0; nt < 8; nt++) {
                o[nt][hh*2]   *= alpha;
                o[nt][hh*2+1] *= alpha;
            }
        }
        // O += P V (P A-frag packed straight from S C-frag; V via LDSM.trans)
        #pragma unroll
        for (int ks = 0; ks < 4; ks++) {
            int kb = ks*16;
            uint32_t pa[4];
            pa[0] = pack2(sacc[2*ks  ][0], sacc[2*ks  ][1]);
            pa[1] = pack2(sacc[2*ks  ][2], sacc[2*ks  ][3]);
            pa[2] = pack2(sacc[2*ks+1][0], sacc[2*ks+1][1]);
            pa[3] = pack2(sacc[2*ks+1][2], sacc[2*ks+1][3]);
            #pragma unroll
            for (int ntp = 0; ntp < 4; ntp++) {
                uint32_t bq[4];
                ldsm4t(bq, &Vsm[buf][(kb + lr + lb1*8)*KS + ntp*16 + lb2*8]);
                mma16(o[2*ntp  ], pa, bq[0], bq[1]);
                mma16(o[2*ntp+1], pa, bq[2], bq[3]);
            }
        }
        __syncthreads();
    }

    // normalize + store bf16
    float inv0 = 1.0f / l2[0];
    float inv1 = 1.0f / l2[1];
    int r0 = q0 + qr0 + g;
    int r1 = r0 + 8;
    #pragma unroll
    for (int nt = 0; nt < 8; nt++) {
        int col = h*HD_ + nt*8 + 2*t;
        if (r0 < LT)
            *(uint32_t*)&g_at[((size_t)(b*LT + r0))*D_ + col] =
                pack2(o[nt][0]*inv0, o[nt][1]*inv0);
        if (r1 < LT)
            *(uint32_t*)&g_at[((size_t)(b*LT + r1))*D_ + col] =
                pack2(o[nt][2]*inv1, o[nt][3]*inv1);
    }
}

// ---------------------------------------------------------------------------
// kernel_launch: ONLY kernel launches (graph-capture friendly).
// ---------------------------------------------------------------------------
extern "C" void kernel_launch(void* const* d_in, const int* in_sizes, int n_in,
                              void* d_out, int out_size)
{
    const float* hv   = (const float*)d_in[0];
    const float* he   = (const float*)d_in[1];
    const float* lnv  = (const float*)d_in[2];
    const float* wq_v = (const float*)d_in[3];
    const float* wk_v = (const float*)d_in[4];
    const float* wv_v = (const float*)d_in[5];
    const float* wo_v = (const float*)d_in[6];
    const float* lne  = (const float*)d_in[7];
    const float* wq_e = (const float*)d_in[8];
    const float* wk_e = (const float*)d_in[9];
    const float* wv_e = (const float*)d_in[10];
    const float* wo_e = (const float*)d_in[11];
    const int*   posv = (const int*)d_in[12];
    const int*   pose = (const int*)d_in[13];
    float* out = (float*)d_out;

    // fused weight convert+transpose to bf16 [n][k]
    wconv_all<<<dim3(30,30,8), 256>>>(wq_v, wk_v, wv_v, wo_v, wq_e, wk_e, wv_e, wo_e);

    rmsnorm_kernel<<<B_*LT, 256>>>(hv, he, lnv, lne);

    // fused QKV projection, both streams
    fgemm<0><<<dim3(25,17,4), 256>>>(nullptr, nullptr, nullptr);

    // rope v2: one warp per row
    rope_kernel<<<(B_*LT)/8, 256>>>(posv, pose);

    attn_tc<<<dim3(17,15,4), 256>>>();

    // fused output projection + residual, both streams
    fgemm<1><<<dim3(15,17,4), 256>>>(out, hv, he);
}